// round 1
// baseline (speedup 1.0000x reference)
#include <cuda_runtime.h>
#include <cuda_bf16.h>

// Problem constants
#define BATCH 16
#define SEQ   1024
#define EMB   768
#define NH    12
#define HD    64          // per-head dim
#define BH    (BATCH*NH)  // 192
#define MTOT  (BATCH*SEQ) // 16384

// Scratch (allocation-free: __device__ globals)
__device__ float g_Q[(size_t)BH*SEQ*HD];            // 48 MB
__device__ float g_K[(size_t)BH*SEQ*HD];            // 48 MB
__device__ float g_V[(size_t)BH*SEQ*HD];            // 48 MB
__device__ float g_S[(size_t)BH*SEQ*SEQ];           // 768 MB scores/att
__device__ float g_C[(size_t)MTOT*EMB];             // 48 MB context

// ---------------------------------------------------------------------------
// Kernel 1: fused QKV projection.
//   C[16384, 2304] = x[16384,768] @ [W_qk | W_v] + bias, scattered into
//   g_Q/g_K (interleaved qk layout: col c in [0,1536): h=c>>7, di=(c&127)>>1,
//   qk=c&1) and g_V (col c in [0,768): h=c>>6, dv=c&63).
// Tile: BM=128, BN=128, BK=16, 256 threads, 8x8 per thread.
// ---------------------------------------------------------------------------
__global__ void __launch_bounds__(256) qkv_kernel(
    const float* __restrict__ x,
    const float* __restrict__ Wqk, const float* __restrict__ bqk,
    const float* __restrict__ Wv,  const float* __restrict__ bv)
{
    const int bm = blockIdx.x;          // 0..127
    const int bn = blockIdx.y;          // 0..17 (12 for qk, 6 for v)
    const bool isV = (bn >= 12);
    const float* Bmat = isV ? Wv : Wqk;
    const int ldb     = isV ? 768 : 1536;
    const int n0      = isV ? (bn - 12) * 128 : bn * 128;
    const float* bias = isV ? bv : bqk;

    __shared__ float As[16][128];
    __shared__ float Bs[16][128];

    const int tid  = threadIdx.x;
    const int trow = (tid >> 4) * 8;
    const int tcol = (tid & 15) * 8;
    const int m0   = bm * 128;

    float acc[8][8] = {};

    for (int kt = 0; kt < EMB; kt += 16) {
        // A: 128x16, transposed store. lin = i*256+tid -> warp reads 64B runs.
        #pragma unroll
        for (int i = 0; i < 2; i++) {
            int lin  = i * 256 + tid;
            int rowA = lin >> 2;
            int k4   = (lin & 3) * 4;
            float4 v = *(const float4*)&x[(size_t)(m0 + rowA) * EMB + kt + k4];
            As[k4+0][rowA] = v.x; As[k4+1][rowA] = v.y;
            As[k4+2][rowA] = v.z; As[k4+3][rowA] = v.w;
        }
        // B: 16x128 direct.
        #pragma unroll
        for (int i = 0; i < 2; i++) {
            int lin  = i * 256 + tid;
            int rowB = lin >> 5;
            int c4   = (lin & 31) * 4;
            *(float4*)&Bs[rowB][c4] =
                *(const float4*)&Bmat[(size_t)(kt + rowB) * ldb + n0 + c4];
        }
        __syncthreads();
        #pragma unroll
        for (int k = 0; k < 16; k++) {
            float a[8], b[8];
            #pragma unroll
            for (int i = 0; i < 8; i++) a[i] = As[k][trow + i];
            #pragma unroll
            for (int j = 0; j < 8; j++) b[j] = Bs[k][tcol + j];
            #pragma unroll
            for (int i = 0; i < 8; i++)
                #pragma unroll
                for (int j = 0; j < 8; j++)
                    acc[i][j] = fmaf(a[i], b[j], acc[i][j]);
        }
        __syncthreads();
    }

    // Epilogue: bias + scatter
    #pragma unroll
    for (int i = 0; i < 8; i++) {
        int gm = m0 + trow + i;
        int bb = gm >> 10;           // batch
        int nn = gm & 1023;          // seq pos
        #pragma unroll
        for (int j = 0; j < 8; j++) {
            int c = n0 + tcol + j;
            float val = acc[i][j] + bias[c];
            if (isV) {
                int h = c >> 6, dv = c & 63;
                g_V[(((size_t)(bb * NH + h)) * SEQ + nn) * HD + dv] = val;
            } else {
                int h = c >> 7, rem = c & 127;
                int di = rem >> 1;
                size_t idx = (((size_t)(bb * NH + h)) * SEQ + nn) * HD + di;
                if (rem & 1) g_K[idx] = val; else g_Q[idx] = val;
            }
        }
    }
}

// ---------------------------------------------------------------------------
// Kernel 2: scores = Q @ K^T * (1/8), batched over bh. M=N=1024, K=64 (NT).
// ---------------------------------------------------------------------------
__global__ void __launch_bounds__(256) scores_kernel()
{
    const int bh = blockIdx.z;
    const float* Qm = g_Q + (size_t)bh * SEQ * HD;
    const float* Km = g_K + (size_t)bh * SEQ * HD;
    float* Sout = g_S + ((size_t)bh << 20);

    __shared__ float As[16][128];
    __shared__ float Bs[16][128];

    const int tid  = threadIdx.x;
    const int trow = (tid >> 4) * 8;
    const int tcol = (tid & 15) * 8;
    const int m0   = blockIdx.x * 128;
    const int n0   = blockIdx.y * 128;

    float acc[8][8] = {};

    for (int kt = 0; kt < HD; kt += 16) {
        #pragma unroll
        for (int i = 0; i < 2; i++) {
            int lin = i * 256 + tid;
            int row = lin >> 2;
            int k4  = (lin & 3) * 4;
            float4 va = *(const float4*)&Qm[(size_t)(m0 + row) * HD + kt + k4];
            As[k4+0][row] = va.x; As[k4+1][row] = va.y;
            As[k4+2][row] = va.z; As[k4+3][row] = va.w;
            float4 vb = *(const float4*)&Km[(size_t)(n0 + row) * HD + kt + k4];
            Bs[k4+0][row] = vb.x; Bs[k4+1][row] = vb.y;
            Bs[k4+2][row] = vb.z; Bs[k4+3][row] = vb.w;
        }
        __syncthreads();
        #pragma unroll
        for (int k = 0; k < 16; k++) {
            float a[8], b[8];
            #pragma unroll
            for (int i = 0; i < 8; i++) a[i] = As[k][trow + i];
            #pragma unroll
            for (int j = 0; j < 8; j++) b[j] = Bs[k][tcol + j];
            #pragma unroll
            for (int i = 0; i < 8; i++)
                #pragma unroll
                for (int j = 0; j < 8; j++)
                    acc[i][j] = fmaf(a[i], b[j], acc[i][j]);
        }
        __syncthreads();
    }
    #pragma unroll
    for (int i = 0; i < 8; i++) {
        #pragma unroll
        for (int j = 0; j < 8; j += 4) {
            float4 v;
            v.x = acc[i][j+0] * 0.125f;
            v.y = acc[i][j+1] * 0.125f;
            v.z = acc[i][j+2] * 0.125f;
            v.w = acc[i][j+3] * 0.125f;
            *(float4*)&Sout[(size_t)(m0 + trow + i) * SEQ + n0 + tcol + j] = v;
        }
    }
}

// ---------------------------------------------------------------------------
// Kernel 3: row softmax over g_S. One block (256 thr) per row of 1024.
// ---------------------------------------------------------------------------
__global__ void __launch_bounds__(256) softmax_kernel()
{
    const size_t base = (size_t)blockIdx.x * SEQ;
    const int tid = threadIdx.x;
    float4 v = *(const float4*)&g_S[base + tid * 4];

    float m = fmaxf(fmaxf(v.x, v.y), fmaxf(v.z, v.w));
    #pragma unroll
    for (int o = 16; o; o >>= 1) m = fmaxf(m, __shfl_xor_sync(~0u, m, o));
    __shared__ float redm[8], reds[8];
    if ((tid & 31) == 0) redm[tid >> 5] = m;
    __syncthreads();
    float mx = redm[0];
    #pragma unroll
    for (int i = 1; i < 8; i++) mx = fmaxf(mx, redm[i]);

    float e0 = __expf(v.x - mx), e1 = __expf(v.y - mx);
    float e2 = __expf(v.z - mx), e3 = __expf(v.w - mx);
    float s = e0 + e1 + e2 + e3;
    #pragma unroll
    for (int o = 16; o; o >>= 1) s += __shfl_xor_sync(~0u, s, o);
    if ((tid & 31) == 0) reds[tid >> 5] = s;
    __syncthreads();
    float tot = reds[0];
    #pragma unroll
    for (int i = 1; i < 8; i++) tot += reds[i];
    float inv = 1.0f / tot;

    float4 o4 = { e0 * inv, e1 * inv, e2 * inv, e3 * inv };
    *(float4*)&g_S[base + tid * 4] = o4;
}

// ---------------------------------------------------------------------------
// Kernel 4: ctx = att @ V, batched. M=1024, N=64, K=1024 (NN).
// Tile: BM=128, BN=64, BK=16, 256 threads, 8x4 per thread.
// Writes directly into [B, N, H*64] layout (g_C).
// ---------------------------------------------------------------------------
__global__ void __launch_bounds__(256) av_kernel()
{
    const int bh = blockIdx.z;
    const int bb = bh / NH;
    const int h  = bh % NH;
    const float* Am = g_S + ((size_t)bh << 20);
    const float* Vm = g_V + (size_t)bh * SEQ * HD;

    __shared__ float As[16][128];
    __shared__ float Bs[16][64];

    const int tid  = threadIdx.x;
    const int trow = (tid >> 4) * 8;
    const int tcol = (tid & 15) * 4;
    const int m0   = blockIdx.x * 128;

    float acc[8][4] = {};

    for (int kt = 0; kt < SEQ; kt += 16) {
        #pragma unroll
        for (int i = 0; i < 2; i++) {
            int lin = i * 256 + tid;
            int row = lin >> 2;
            int k4  = (lin & 3) * 4;
            float4 va = *(const float4*)&Am[(size_t)(m0 + row) * SEQ + kt + k4];
            As[k4+0][row] = va.x; As[k4+1][row] = va.y;
            As[k4+2][row] = va.z; As[k4+3][row] = va.w;
        }
        {
            int rowB = tid >> 4;         // 0..15
            int c4   = (tid & 15) * 4;   // 0..60
            *(float4*)&Bs[rowB][c4] =
                *(const float4*)&Vm[(size_t)(kt + rowB) * HD + c4];
        }
        __syncthreads();
        #pragma unroll
        for (int k = 0; k < 16; k++) {
            float a[8], b[4];
            #pragma unroll
            for (int i = 0; i < 8; i++) a[i] = As[k][trow + i];
            #pragma unroll
            for (int j = 0; j < 4; j++) b[j] = Bs[k][tcol + j];
            #pragma unroll
            for (int i = 0; i < 8; i++)
                #pragma unroll
                for (int j = 0; j < 4; j++)
                    acc[i][j] = fmaf(a[i], b[j], acc[i][j]);
        }
        __syncthreads();
    }
    #pragma unroll
    for (int i = 0; i < 8; i++) {
        int nn = m0 + trow + i;
        float4 v = { acc[i][0], acc[i][1], acc[i][2], acc[i][3] };
        *(float4*)&g_C[((size_t)(bb * SEQ + nn)) * EMB + h * HD + tcol] = v;
    }
}

// ---------------------------------------------------------------------------
// Kernel 5: out = ctx @ W_proj + b_proj. M=16384, N=768, K=768 (NN).
// ---------------------------------------------------------------------------
__global__ void __launch_bounds__(256) proj_kernel(
    const float* __restrict__ Wp, const float* __restrict__ bp,
    float* __restrict__ out)
{
    __shared__ float As[16][128];
    __shared__ float Bs[16][128];

    const int tid  = threadIdx.x;
    const int trow = (tid >> 4) * 8;
    const int tcol = (tid & 15) * 8;
    const int m0   = blockIdx.x * 128;
    const int n0   = blockIdx.y * 128;

    float acc[8][8] = {};

    for (int kt = 0; kt < EMB; kt += 16) {
        #pragma unroll
        for (int i = 0; i < 2; i++) {
            int lin  = i * 256 + tid;
            int rowA = lin >> 2;
            int k4   = (lin & 3) * 4;
            float4 v = *(const float4*)&g_C[(size_t)(m0 + rowA) * EMB + kt + k4];
            As[k4+0][rowA] = v.x; As[k4+1][rowA] = v.y;
            As[k4+2][rowA] = v.z; As[k4+3][rowA] = v.w;
        }
        #pragma unroll
        for (int i = 0; i < 2; i++) {
            int lin  = i * 256 + tid;
            int rowB = lin >> 5;
            int c4   = (lin & 31) * 4;
            *(float4*)&Bs[rowB][c4] =
                *(const float4*)&Wp[(size_t)(kt + rowB) * EMB + n0 + c4];
        }
        __syncthreads();
        #pragma unroll
        for (int k = 0; k < 16; k++) {
            float a[8], b[8];
            #pragma unroll
            for (int i = 0; i < 8; i++) a[i] = As[k][trow + i];
            #pragma unroll
            for (int j = 0; j < 8; j++) b[j] = Bs[k][tcol + j];
            #pragma unroll
            for (int i = 0; i < 8; i++)
                #pragma unroll
                for (int j = 0; j < 8; j++)
                    acc[i][j] = fmaf(a[i], b[j], acc[i][j]);
        }
        __syncthreads();
    }
    #pragma unroll
    for (int i = 0; i < 8; i++) {
        int gm = m0 + trow + i;
        #pragma unroll
        for (int j = 0; j < 8; j += 4) {
            int c = n0 + tcol + j;
            float4 v;
            v.x = acc[i][j+0] + bp[c+0];
            v.y = acc[i][j+1] + bp[c+1];
            v.z = acc[i][j+2] + bp[c+2];
            v.w = acc[i][j+3] + bp[c+3];
            *(float4*)&out[(size_t)gm * EMB + c] = v;
        }
    }
}

// ---------------------------------------------------------------------------
extern "C" void kernel_launch(void* const* d_in, const int* in_sizes, int n_in,
                              void* d_out, int out_size)
{
    const float* x   = (const float*)d_in[0];
    const float* Wqk = (const float*)d_in[1];
    const float* bqk = (const float*)d_in[2];
    const float* Wv  = (const float*)d_in[3];
    const float* bv  = (const float*)d_in[4];
    const float* Wp  = (const float*)d_in[5];
    const float* bp  = (const float*)d_in[6];
    float* out = (float*)d_out;

    dim3 g1(MTOT / 128, 18);              // 12 qk col-tiles + 6 v col-tiles
    qkv_kernel<<<g1, 256>>>(x, Wqk, bqk, Wv, bv);

    dim3 g2(SEQ / 128, SEQ / 128, BH);
    scores_kernel<<<g2, 256>>>();

    softmax_kernel<<<BH * SEQ, 256>>>();

    dim3 g3(SEQ / 128, 1, BH);
    av_kernel<<<g3, 256>>>();

    dim3 g4(MTOT / 128, EMB / 128);
    proj_kernel<<<g4, 256>>>(Wp, bp, out);
}

// round 5
// speedup vs baseline: 2.0982x; 2.0982x over previous
#include <cuda_runtime.h>
#include <cuda_bf16.h>
#include <cstdint>

// Problem constants
#define BATCH 16
#define SEQ   1024
#define EMB   768
#define NH    12
#define HD    64
#define BH    (BATCH*NH)  // 192
#define MTOT  (BATCH*SEQ) // 16384

// Scratch (allocation-free: __device__ globals)
__device__ float g_Q[(size_t)BH*SEQ*HD];
__device__ float g_K[(size_t)BH*SEQ*HD];
__device__ float g_V[(size_t)BH*SEQ*HD];
__device__ float g_S[(size_t)BH*SEQ*SEQ];   // 768 MB scores/att
__device__ float g_C[(size_t)MTOT*EMB];

// ---------------------------------------------------------------------------
// tf32 helpers
// ---------------------------------------------------------------------------
__device__ __forceinline__ uint32_t to_tf32(float f) {
    uint32_t u;
    asm("cvt.rna.tf32.f32 %0, %1;" : "=r"(u) : "f"(f));
    return u;
}

__device__ __forceinline__ void mma8(float* c, const uint32_t* a, const uint32_t* b) {
    asm volatile(
        "mma.sync.aligned.m16n8k8.row.col.f32.tf32.tf32.f32 "
        "{%0,%1,%2,%3},{%4,%5,%6,%7},{%8,%9},{%0,%1,%2,%3};"
        : "+f"(c[0]), "+f"(c[1]), "+f"(c[2]), "+f"(c[3])
        : "r"(a[0]), "r"(a[1]), "r"(a[2]), "r"(a[3]), "r"(b[0]), "r"(b[1]));
}

// SMEM strides (banks: A-frag bank = (4g+tig)%32 distinct; B-frag = (8tig+g)%32 distinct)
#define LDA_S 36     // A tile [128][36] (m-major, k inner)
#define LDB_S 136    // NN B tile [32][136] (k-major, n inner)
#define LDBV_S 72    // av B tile [32][72]

// ---------------------------------------------------------------------------
// Kernel 1: fused QKV projection (tf32 MMA).
// block tile 128x128, 128 threads (4 warps, 2x2), warp tile 64x64, BK=32.
// ---------------------------------------------------------------------------
__global__ void __launch_bounds__(128) qkv_kernel(
    const float* __restrict__ x,
    const float* __restrict__ Wqk, const float* __restrict__ bqk,
    const float* __restrict__ Wv,  const float* __restrict__ bv)
{
    const int bn  = blockIdx.y;
    const bool isV = (bn >= 12);
    const float* Bmat = isV ? Wv : Wqk;
    const int ldb     = isV ? 768 : 1536;
    const int n0      = isV ? (bn - 12) * 128 : bn * 128;
    const float* bias = isV ? bv : bqk;
    const int m0 = blockIdx.x * 128;

    __shared__ uint32_t As[128 * LDA_S];
    __shared__ uint32_t Bs[32 * LDB_S];

    const int tid = threadIdx.x;
    const int w = tid >> 5, lane = tid & 31;
    const int g = lane >> 2, tig = lane & 3;
    const int wm = (w >> 1) * 64, wn = (w & 1) * 64;

    float acc[4][8][4];
    #pragma unroll
    for (int i = 0; i < 4; i++)
        #pragma unroll
        for (int j = 0; j < 8; j++)
            #pragma unroll
            for (int r = 0; r < 4; r++) acc[i][j][r] = 0.f;

    for (int kt = 0; kt < EMB; kt += 32) {
        #pragma unroll
        for (int p = 0; p < 8; p++) {
            int lin = p * 128 + tid;
            int r = lin >> 3, k4 = (lin & 7) << 2;
            float4 v = *(const float4*)&x[(size_t)(m0 + r) * EMB + kt + k4];
            uint4 t = { to_tf32(v.x), to_tf32(v.y), to_tf32(v.z), to_tf32(v.w) };
            *(uint4*)&As[r * LDA_S + k4] = t;
        }
        #pragma unroll
        for (int p = 0; p < 8; p++) {
            int lin = p * 128 + tid;
            int r = lin >> 5, c4 = (lin & 31) << 2;
            float4 v = *(const float4*)&Bmat[(size_t)(kt + r) * ldb + n0 + c4];
            uint4 t = { to_tf32(v.x), to_tf32(v.y), to_tf32(v.z), to_tf32(v.w) };
            *(uint4*)&Bs[r * LDB_S + c4] = t;
        }
        __syncthreads();
        #pragma unroll
        for (int ks = 0; ks < 4; ks++) {
            uint32_t a[4][4], b[8][2];
            #pragma unroll
            for (int mi = 0; mi < 4; mi++) {
                int base = (wm + mi * 16 + g) * LDA_S + ks * 8 + tig;
                a[mi][0] = As[base];
                a[mi][1] = As[base + 8 * LDA_S];
                a[mi][2] = As[base + 4];
                a[mi][3] = As[base + 8 * LDA_S + 4];
            }
            #pragma unroll
            for (int ni = 0; ni < 8; ni++) {
                int col = wn + ni * 8 + g;
                b[ni][0] = Bs[(ks * 8 + tig) * LDB_S + col];
                b[ni][1] = Bs[(ks * 8 + tig + 4) * LDB_S + col];
            }
            #pragma unroll
            for (int mi = 0; mi < 4; mi++)
                #pragma unroll
                for (int ni = 0; ni < 8; ni++)
                    mma8(acc[mi][ni], a[mi], b[ni]);
        }
        __syncthreads();
    }

    // Epilogue: bias + scatter (Q/K interleaved or V)
    #pragma unroll
    for (int mi = 0; mi < 4; mi++) {
        #pragma unroll
        for (int rr = 0; rr < 2; rr++) {
            int gm = m0 + wm + mi * 16 + g + rr * 8;
            int bb = gm >> 10, nn = gm & 1023;
            #pragma unroll
            for (int ni = 0; ni < 8; ni++) {
                #pragma unroll
                for (int cc = 0; cc < 2; cc++) {
                    int c = n0 + wn + ni * 8 + tig * 2 + cc;
                    float val = acc[mi][ni][rr * 2 + cc] + bias[c];
                    if (isV) {
                        int h = c >> 6, dv = c & 63;
                        g_V[(((size_t)(bb * NH + h)) * SEQ + nn) * HD + dv] = val;
                    } else {
                        int h = c >> 7, rem = c & 127;
                        int di = rem >> 1;
                        size_t idx = (((size_t)(bb * NH + h)) * SEQ + nn) * HD + di;
                        if (rem & 1) g_K[idx] = val; else g_Q[idx] = val;
                    }
                }
            }
        }
    }
}

// ---------------------------------------------------------------------------
// Kernel 2: scores = Q @ K^T * 0.125 (NT, tf32 MMA). K rows are naturally
// col-major B for mma row.col.
// ---------------------------------------------------------------------------
__global__ void __launch_bounds__(128) scores_kernel()
{
    const int bh = blockIdx.z;
    const float* Qm = g_Q + (size_t)bh * SEQ * HD;
    const float* Km = g_K + (size_t)bh * SEQ * HD;
    float* Sout = g_S + ((size_t)bh << 20);

    __shared__ uint32_t As[128 * LDA_S];
    __shared__ uint32_t Ks[128 * LDA_S];

    const int tid = threadIdx.x;
    const int w = tid >> 5, lane = tid & 31;
    const int g = lane >> 2, tig = lane & 3;
    const int wm = (w >> 1) * 64, wn = (w & 1) * 64;
    const int m0 = blockIdx.x * 128, n0 = blockIdx.y * 128;

    float acc[4][8][4];
    #pragma unroll
    for (int i = 0; i < 4; i++)
        #pragma unroll
        for (int j = 0; j < 8; j++)
            #pragma unroll
            for (int r = 0; r < 4; r++) acc[i][j][r] = 0.f;

    for (int kt = 0; kt < HD; kt += 32) {
        #pragma unroll
        for (int p = 0; p < 8; p++) {
            int lin = p * 128 + tid;
            int r = lin >> 3, k4 = (lin & 7) << 2;
            float4 va = *(const float4*)&Qm[(size_t)(m0 + r) * HD + kt + k4];
            uint4 ta = { to_tf32(va.x), to_tf32(va.y), to_tf32(va.z), to_tf32(va.w) };
            *(uint4*)&As[r * LDA_S + k4] = ta;
            float4 vb = *(const float4*)&Km[(size_t)(n0 + r) * HD + kt + k4];
            uint4 tb = { to_tf32(vb.x), to_tf32(vb.y), to_tf32(vb.z), to_tf32(vb.w) };
            *(uint4*)&Ks[r * LDA_S + k4] = tb;
        }
        __syncthreads();
        #pragma unroll
        for (int ks = 0; ks < 4; ks++) {
            uint32_t a[4][4], b[8][2];
            #pragma unroll
            for (int mi = 0; mi < 4; mi++) {
                int base = (wm + mi * 16 + g) * LDA_S + ks * 8 + tig;
                a[mi][0] = As[base];
                a[mi][1] = As[base + 8 * LDA_S];
                a[mi][2] = As[base + 4];
                a[mi][3] = As[base + 8 * LDA_S + 4];
            }
            #pragma unroll
            for (int ni = 0; ni < 8; ni++) {
                int base = (wn + ni * 8 + g) * LDA_S + ks * 8 + tig;
                b[ni][0] = Ks[base];
                b[ni][1] = Ks[base + 4];
            }
            #pragma unroll
            for (int mi = 0; mi < 4; mi++)
                #pragma unroll
                for (int ni = 0; ni < 8; ni++)
                    mma8(acc[mi][ni], a[mi], b[ni]);
        }
        __syncthreads();
    }

    #pragma unroll
    for (int mi = 0; mi < 4; mi++)
        #pragma unroll
        for (int rr = 0; rr < 2; rr++) {
            int row = m0 + wm + mi * 16 + g + rr * 8;
            #pragma unroll
            for (int ni = 0; ni < 8; ni++) {
                int col = n0 + wn + ni * 8 + tig * 2;
                float2 v = { acc[mi][ni][rr * 2] * 0.125f,
                             acc[mi][ni][rr * 2 + 1] * 0.125f };
                *(float2*)&Sout[(size_t)row * SEQ + col] = v;
            }
        }
}

// ---------------------------------------------------------------------------
// Kernel 3: row softmax over g_S (unchanged).
// ---------------------------------------------------------------------------
__global__ void __launch_bounds__(256) softmax_kernel()
{
    const size_t base = (size_t)blockIdx.x * SEQ;
    const int tid = threadIdx.x;
    float4 v = *(const float4*)&g_S[base + tid * 4];

    float m = fmaxf(fmaxf(v.x, v.y), fmaxf(v.z, v.w));
    #pragma unroll
    for (int o = 16; o; o >>= 1) m = fmaxf(m, __shfl_xor_sync(~0u, m, o));
    __shared__ float redm[8], reds[8];
    if ((tid & 31) == 0) redm[tid >> 5] = m;
    __syncthreads();
    float mx = redm[0];
    #pragma unroll
    for (int i = 1; i < 8; i++) mx = fmaxf(mx, redm[i]);

    float e0 = __expf(v.x - mx), e1 = __expf(v.y - mx);
    float e2 = __expf(v.z - mx), e3 = __expf(v.w - mx);
    float s = e0 + e1 + e2 + e3;
    #pragma unroll
    for (int o = 16; o; o >>= 1) s += __shfl_xor_sync(~0u, s, o);
    if ((tid & 31) == 0) reds[tid >> 5] = s;
    __syncthreads();
    float tot = reds[0];
    #pragma unroll
    for (int i = 1; i < 8; i++) tot += reds[i];
    float inv = 1.0f / tot;

    float4 o4 = { e0 * inv, e1 * inv, e2 * inv, e3 * inv };
    *(float4*)&g_S[base + tid * 4] = o4;
}

// ---------------------------------------------------------------------------
// Kernel 4: ctx = att @ V (NN, tf32 MMA). block 128x64, warp tile 64x32.
// ---------------------------------------------------------------------------
__global__ void __launch_bounds__(128) av_kernel()
{
    const int bh = blockIdx.z;
    const int bb = bh / NH, h = bh % NH;
    const float* Am = g_S + ((size_t)bh << 20);
    const float* Vm = g_V + (size_t)bh * SEQ * HD;

    __shared__ uint32_t As[128 * LDA_S];
    __shared__ uint32_t Bs[32 * LDBV_S];

    const int tid = threadIdx.x;
    const int w = tid >> 5, lane = tid & 31;
    const int g = lane >> 2, tig = lane & 3;
    const int wm = (w >> 1) * 64, wn = (w & 1) * 32;
    const int m0 = blockIdx.x * 128;

    float acc[4][4][4];
    #pragma unroll
    for (int i = 0; i < 4; i++)
        #pragma unroll
        for (int j = 0; j < 4; j++)
            #pragma unroll
            for (int r = 0; r < 4; r++) acc[i][j][r] = 0.f;

    for (int kt = 0; kt < SEQ; kt += 32) {
        #pragma unroll
        for (int p = 0; p < 8; p++) {
            int lin = p * 128 + tid;
            int r = lin >> 3, k4 = (lin & 7) << 2;
            float4 v = *(const float4*)&Am[(size_t)(m0 + r) * SEQ + kt + k4];
            uint4 t = { to_tf32(v.x), to_tf32(v.y), to_tf32(v.z), to_tf32(v.w) };
            *(uint4*)&As[r * LDA_S + k4] = t;
        }
        #pragma unroll
        for (int p = 0; p < 4; p++) {
            int lin = p * 128 + tid;
            int r = lin >> 4, c4 = (lin & 15) << 2;
            float4 v = *(const float4*)&Vm[(size_t)(kt + r) * HD + c4];
            uint4 t = { to_tf32(v.x), to_tf32(v.y), to_tf32(v.z), to_tf32(v.w) };
            *(uint4*)&Bs[r * LDBV_S + c4] = t;
        }
        __syncthreads();
        #pragma unroll
        for (int ks = 0; ks < 4; ks++) {
            uint32_t a[4][4], b[4][2];
            #pragma unroll
            for (int mi = 0; mi < 4; mi++) {
                int base = (wm + mi * 16 + g) * LDA_S + ks * 8 + tig;
                a[mi][0] = As[base];
                a[mi][1] = As[base + 8 * LDA_S];
                a[mi][2] = As[base + 4];
                a[mi][3] = As[base + 8 * LDA_S + 4];
            }
            #pragma unroll
            for (int ni = 0; ni < 4; ni++) {
                int col = wn + ni * 8 + g;
                b[ni][0] = Bs[(ks * 8 + tig) * LDBV_S + col];
                b[ni][1] = Bs[(ks * 8 + tig + 4) * LDBV_S + col];
            }
            #pragma unroll
            for (int mi = 0; mi < 4; mi++)
                #pragma unroll
                for (int ni = 0; ni < 4; ni++)
                    mma8(acc[mi][ni], a[mi], b[ni]);
        }
        __syncthreads();
    }

    #pragma unroll
    for (int mi = 0; mi < 4; mi++)
        #pragma unroll
        for (int rr = 0; rr < 2; rr++) {
            int nn = m0 + wm + mi * 16 + g + rr * 8;
            #pragma unroll
            for (int ni = 0; ni < 4; ni++) {
                int col = wn + ni * 8 + tig * 2;
                float2 v = { acc[mi][ni][rr * 2], acc[mi][ni][rr * 2 + 1] };
                *(float2*)&g_C[((size_t)(bb * SEQ + nn)) * EMB + h * HD + col] = v;
            }
        }
}

// ---------------------------------------------------------------------------
// Kernel 5: out = ctx @ W_proj + b_proj (NN, tf32 MMA).
// ---------------------------------------------------------------------------
__global__ void __launch_bounds__(128) proj_kernel(
    const float* __restrict__ Wp, const float* __restrict__ bp,
    float* __restrict__ out)
{
    __shared__ uint32_t As[128 * LDA_S];
    __shared__ uint32_t Bs[32 * LDB_S];

    const int tid = threadIdx.x;
    const int w = tid >> 5, lane = tid & 31;
    const int g = lane >> 2, tig = lane & 3;
    const int wm = (w >> 1) * 64, wn = (w & 1) * 64;
    const int m0 = blockIdx.x * 128, n0 = blockIdx.y * 128;

    float acc[4][8][4];
    #pragma unroll
    for (int i = 0; i < 4; i++)
        #pragma unroll
        for (int j = 0; j < 8; j++)
            #pragma unroll
            for (int r = 0; r < 4; r++) acc[i][j][r] = 0.f;

    for (int kt = 0; kt < EMB; kt += 32) {
        #pragma unroll
        for (int p = 0; p < 8; p++) {
            int lin = p * 128 + tid;
            int r = lin >> 3, k4 = (lin & 7) << 2;
            float4 v = *(const float4*)&g_C[(size_t)(m0 + r) * EMB + kt + k4];
            uint4 t = { to_tf32(v.x), to_tf32(v.y), to_tf32(v.z), to_tf32(v.w) };
            *(uint4*)&As[r * LDA_S + k4] = t;
        }
        #pragma unroll
        for (int p = 0; p < 8; p++) {
            int lin = p * 128 + tid;
            int r = lin >> 5, c4 = (lin & 31) << 2;
            float4 v = *(const float4*)&Wp[(size_t)(kt + r) * EMB + n0 + c4];
            uint4 t = { to_tf32(v.x), to_tf32(v.y), to_tf32(v.z), to_tf32(v.w) };
            *(uint4*)&Bs[r * LDB_S + c4] = t;
        }
        __syncthreads();
        #pragma unroll
        for (int ks = 0; ks < 4; ks++) {
            uint32_t a[4][4], b[8][2];
            #pragma unroll
            for (int mi = 0; mi < 4; mi++) {
                int base = (wm + mi * 16 + g) * LDA_S + ks * 8 + tig;
                a[mi][0] = As[base];
                a[mi][1] = As[base + 8 * LDA_S];
                a[mi][2] = As[base + 4];
                a[mi][3] = As[base + 8 * LDA_S + 4];
            }
            #pragma unroll
            for (int ni = 0; ni < 8; ni++) {
                int col = wn + ni * 8 + g;
                b[ni][0] = Bs[(ks * 8 + tig) * LDB_S + col];
                b[ni][1] = Bs[(ks * 8 + tig + 4) * LDB_S + col];
            }
            #pragma unroll
            for (int mi = 0; mi < 4; mi++)
                #pragma unroll
                for (int ni = 0; ni < 8; ni++)
                    mma8(acc[mi][ni], a[mi], b[ni]);
        }
        __syncthreads();
    }

    #pragma unroll
    for (int mi = 0; mi < 4; mi++)
        #pragma unroll
        for (int rr = 0; rr < 2; rr++) {
            int gm = m0 + wm + mi * 16 + g + rr * 8;
            #pragma unroll
            for (int ni = 0; ni < 8; ni++) {
                int c = n0 + wn + ni * 8 + tig * 2;
                float2 v = { acc[mi][ni][rr * 2] + bp[c],
                             acc[mi][ni][rr * 2 + 1] + bp[c + 1] };
                *(float2*)&out[(size_t)gm * EMB + c] = v;
            }
        }
}

// ---------------------------------------------------------------------------
extern "C" void kernel_launch(void* const* d_in, const int* in_sizes, int n_in,
                              void* d_out, int out_size)
{
    const float* x   = (const float*)d_in[0];
    const float* Wqk = (const float*)d_in[1];
    const float* bqk = (const float*)d_in[2];
    const float* Wv  = (const float*)d_in[3];
    const float* bv  = (const float*)d_in[4];
    const float* Wp  = (const float*)d_in[5];
    const float* bp  = (const float*)d_in[6];
    float* out = (float*)d_out;

    dim3 g1(MTOT / 128, 18);
    qkv_kernel<<<g1, 128>>>(x, Wqk, bqk, Wv, bv);

    dim3 g2(SEQ / 128, SEQ / 128, BH);
    scores_kernel<<<g2, 128>>>();

    softmax_kernel<<<BH * SEQ, 256>>>();

    dim3 g3(SEQ / 128, 1, BH);
    av_kernel<<<g3, 128>>>();

    dim3 g4(MTOT / 128, EMB / 128);
    proj_kernel<<<g4, 128>>>(Wp, bp, out);
}

// round 9
// speedup vs baseline: 2.9198x; 1.3915x over previous
#include <cuda_runtime.h>
#include <cuda_bf16.h>
#include <cstdint>

// Problem constants
#define BATCH 16
#define SEQ   1024
#define EMB   768
#define NH    12
#define HD    64
#define BH    (BATCH*NH)  // 192
#define MTOT  (BATCH*SEQ) // 16384

// Scratch (allocation-free: __device__ globals)
__device__ float g_Q[(size_t)BH*SEQ*HD];
__device__ float g_K[(size_t)BH*SEQ*HD];
__device__ float g_V[(size_t)BH*SEQ*HD];
__device__ float g_C[(size_t)MTOT*EMB];

// ---------------------------------------------------------------------------
// tf32 helpers
// ---------------------------------------------------------------------------
__device__ __forceinline__ uint32_t to_tf32(float f) {
    uint32_t u;
    asm("cvt.rna.tf32.f32 %0, %1;" : "=r"(u) : "f"(f));
    return u;
}

__device__ __forceinline__ void mma8(float* c, const uint32_t* a, const uint32_t* b) {
    asm volatile(
        "mma.sync.aligned.m16n8k8.row.col.f32.tf32.tf32.f32 "
        "{%0,%1,%2,%3},{%4,%5,%6,%7},{%8,%9},{%0,%1,%2,%3};"
        : "+f"(c[0]), "+f"(c[1]), "+f"(c[2]), "+f"(c[3])
        : "r"(a[0]), "r"(a[1]), "r"(a[2]), "r"(a[3]), "r"(b[0]), "r"(b[1]));
}

// SMEM strides
#define LDA_S 36     // GEMM A tile [128][36] (m-major, k inner), stride%32==4
#define LDB_S 136    // GEMM NN B tile [32][136], stride%32==8

// Flash strides
#define LDK 68       // K tile [32][68], %32==4 -> conflict-free NT B-frag
#define LDV 72       // V tile [32][72], %32==8 -> conflict-free NN B-frag
#define LDP 36       // P tile [128][36], %32==4 -> conflict-free A-frag

// ---------------------------------------------------------------------------
// Kernel 1: fused QKV projection (tf32 MMA). 128x128 block tile, 4 warps.
// ---------------------------------------------------------------------------
__global__ void __launch_bounds__(128) qkv_kernel(
    const float* __restrict__ x,
    const float* __restrict__ Wqk, const float* __restrict__ bqk,
    const float* __restrict__ Wv,  const float* __restrict__ bv)
{
    const int bn  = blockIdx.y;
    const bool isV = (bn >= 12);
    const float* Bmat = isV ? Wv : Wqk;
    const int ldb     = isV ? 768 : 1536;
    const int n0      = isV ? (bn - 12) * 128 : bn * 128;
    const float* bias = isV ? bv : bqk;
    const int m0 = blockIdx.x * 128;

    __shared__ uint32_t As[128 * LDA_S];
    __shared__ uint32_t Bs[32 * LDB_S];

    const int tid = threadIdx.x;
    const int w = tid >> 5, lane = tid & 31;
    const int g = lane >> 2, tig = lane & 3;
    const int wm = (w >> 1) * 64, wn = (w & 1) * 64;

    float acc[4][8][4];
    #pragma unroll
    for (int i = 0; i < 4; i++)
        #pragma unroll
        for (int j = 0; j < 8; j++)
            #pragma unroll
            for (int r = 0; r < 4; r++) acc[i][j][r] = 0.f;

    for (int kt = 0; kt < EMB; kt += 32) {
        #pragma unroll
        for (int p = 0; p < 8; p++) {
            int lin = p * 128 + tid;
            int r = lin >> 3, k4 = (lin & 7) << 2;
            float4 v = *(const float4*)&x[(size_t)(m0 + r) * EMB + kt + k4];
            uint4 t = { to_tf32(v.x), to_tf32(v.y), to_tf32(v.z), to_tf32(v.w) };
            *(uint4*)&As[r * LDA_S + k4] = t;
        }
        #pragma unroll
        for (int p = 0; p < 8; p++) {
            int lin = p * 128 + tid;
            int r = lin >> 5, c4 = (lin & 31) << 2;
            float4 v = *(const float4*)&Bmat[(size_t)(kt + r) * ldb + n0 + c4];
            uint4 t = { to_tf32(v.x), to_tf32(v.y), to_tf32(v.z), to_tf32(v.w) };
            *(uint4*)&Bs[r * LDB_S + c4] = t;
        }
        __syncthreads();
        #pragma unroll
        for (int ks = 0; ks < 4; ks++) {
            uint32_t a[4][4], b[8][2];
            #pragma unroll
            for (int mi = 0; mi < 4; mi++) {
                int base = (wm + mi * 16 + g) * LDA_S + ks * 8 + tig;
                a[mi][0] = As[base];
                a[mi][1] = As[base + 8 * LDA_S];
                a[mi][2] = As[base + 4];
                a[mi][3] = As[base + 8 * LDA_S + 4];
            }
            #pragma unroll
            for (int ni = 0; ni < 8; ni++) {
                int col = wn + ni * 8 + g;
                b[ni][0] = Bs[(ks * 8 + tig) * LDB_S + col];
                b[ni][1] = Bs[(ks * 8 + tig + 4) * LDB_S + col];
            }
            #pragma unroll
            for (int mi = 0; mi < 4; mi++)
                #pragma unroll
                for (int ni = 0; ni < 8; ni++)
                    mma8(acc[mi][ni], a[mi], b[ni]);
        }
        __syncthreads();
    }

    #pragma unroll
    for (int mi = 0; mi < 4; mi++) {
        #pragma unroll
        for (int rr = 0; rr < 2; rr++) {
            int gm = m0 + wm + mi * 16 + g + rr * 8;
            int bb = gm >> 10, nn = gm & 1023;
            #pragma unroll
            for (int ni = 0; ni < 8; ni++) {
                #pragma unroll
                for (int cc = 0; cc < 2; cc++) {
                    int c = n0 + wn + ni * 8 + tig * 2 + cc;
                    float val = acc[mi][ni][rr * 2 + cc] + bias[c];
                    if (isV) {
                        int h = c >> 6, dv = c & 63;
                        g_V[(((size_t)(bb * NH + h)) * SEQ + nn) * HD + dv] = val;
                    } else {
                        int h = c >> 7, rem = c & 127;
                        int di = rem >> 1;
                        size_t idx = (((size_t)(bb * NH + h)) * SEQ + nn) * HD + di;
                        if (rem & 1) g_K[idx] = val; else g_Q[idx] = val;
                    }
                }
            }
        }
    }
}

// ---------------------------------------------------------------------------
// Kernel 2: fused flash attention (STATIC smem <= 48KB, no host API needed).
// Grid (SEQ/128, BH). 128 threads = 4 warps; warp w owns q-rows [32w,32w+32)
// across the FULL kv tile of 32, so softmax stats stay in-warp.
// Q fragments held in registers (loaded once via 2-half staging through Ps).
// SMEM: Ks[32*68] + Vs[32*72] + Ps[128*36]  = 35.5 KB.
// ---------------------------------------------------------------------------
__global__ void __launch_bounds__(128) flash_kernel()
{
    __shared__ uint32_t Ks[32 * LDK];
    __shared__ uint32_t Vs[32 * LDV];
    __shared__ uint32_t Ps[128 * LDP];

    const int bh = blockIdx.y;
    const int bb = bh / NH, h = bh % NH;
    const int q0 = blockIdx.x * 128;
    const float* Qg = g_Q + (size_t)bh * SEQ * HD;
    const float* Kg = g_K + (size_t)bh * SEQ * HD;
    const float* Vg = g_V + (size_t)bh * SEQ * HD;

    const int tid = threadIdx.x;
    const int w = tid >> 5, lane = tid & 31;
    const int g = lane >> 2, tig = lane & 3;
    const int wm = w * 32;

    // --- Load Q fragments into registers (scale 1/8 folded in). ---
    // Two halves of 32 cols staged through Ps.
    uint32_t qa[2][8][4];   // [mi][ks][reg]
    #pragma unroll
    for (int half = 0; half < 2; half++) {
        #pragma unroll
        for (int p = 0; p < 8; p++) {
            int lin = p * 128 + tid;
            int r = lin >> 3, c4 = (lin & 7) << 2;
            float4 v = *(const float4*)&Qg[(size_t)(q0 + r) * HD + half * 32 + c4];
            uint4 t = { to_tf32(v.x * 0.125f), to_tf32(v.y * 0.125f),
                        to_tf32(v.z * 0.125f), to_tf32(v.w * 0.125f) };
            *(uint4*)&Ps[r * LDP + c4] = t;
        }
        __syncthreads();
        #pragma unroll
        for (int ksl = 0; ksl < 4; ksl++) {
            #pragma unroll
            for (int mi = 0; mi < 2; mi++) {
                int base = (wm + mi * 16 + g) * LDP + ksl * 8 + tig;
                qa[mi][half * 4 + ksl][0] = Ps[base];
                qa[mi][half * 4 + ksl][1] = Ps[base + 8 * LDP];
                qa[mi][half * 4 + ksl][2] = Ps[base + 4];
                qa[mi][half * 4 + ksl][3] = Ps[base + 8 * LDP + 4];
            }
        }
        __syncthreads();
    }

    float O[2][8][4];
    #pragma unroll
    for (int mi = 0; mi < 2; mi++)
        #pragma unroll
        for (int ni = 0; ni < 8; ni++)
            #pragma unroll
            for (int r = 0; r < 4; r++) O[mi][ni][r] = 0.f;
    float m[4] = { -1e30f, -1e30f, -1e30f, -1e30f };
    float l[4] = { 0.f, 0.f, 0.f, 0.f };

    for (int kt = 0; kt < SEQ; kt += 32) {
        __syncthreads();   // prior iteration's Ks/Vs reads complete
        // Load K, V tiles (32 rows x 64)
        #pragma unroll
        for (int p = 0; p < 4; p++) {
            int lin = p * 128 + tid;
            int r = lin >> 4, c4 = (lin & 15) << 2;
            float4 vk = *(const float4*)&Kg[(size_t)(kt + r) * HD + c4];
            uint4 tk = { to_tf32(vk.x), to_tf32(vk.y), to_tf32(vk.z), to_tf32(vk.w) };
            *(uint4*)&Ks[r * LDK + c4] = tk;
            float4 vv = *(const float4*)&Vg[(size_t)(kt + r) * HD + c4];
            uint4 tv = { to_tf32(vv.x), to_tf32(vv.y), to_tf32(vv.z), to_tf32(vv.w) };
            *(uint4*)&Vs[r * LDV + c4] = tv;
        }
        __syncthreads();

        // S = Q@K^T (32x32 per warp), k = 64
        float s[2][4][4];
        #pragma unroll
        for (int mi = 0; mi < 2; mi++)
            #pragma unroll
            for (int ni = 0; ni < 4; ni++)
                #pragma unroll
                for (int r = 0; r < 4; r++) s[mi][ni][r] = 0.f;

        #pragma unroll
        for (int ks = 0; ks < 8; ks++) {
            uint32_t b[4][2];
            #pragma unroll
            for (int ni = 0; ni < 4; ni++) {
                int base = (ni * 8 + g) * LDK + ks * 8 + tig;
                b[ni][0] = Ks[base];
                b[ni][1] = Ks[base + 4];
            }
            #pragma unroll
            for (int mi = 0; mi < 2; mi++)
                #pragma unroll
                for (int ni = 0; ni < 4; ni++)
                    mma8(s[mi][ni], qa[mi][ks], b[ni]);
        }

        // Online softmax update (rows in-warp: reduce over tig lanes only)
        float scl[4];
        #pragma unroll
        for (int mi = 0; mi < 2; mi++) {
            #pragma unroll
            for (int rr = 0; rr < 2; rr++) {
                int si = mi * 2 + rr;
                float rmax = -1e30f;
                #pragma unroll
                for (int ni = 0; ni < 4; ni++) {
                    rmax = fmaxf(rmax, s[mi][ni][rr * 2]);
                    rmax = fmaxf(rmax, s[mi][ni][rr * 2 + 1]);
                }
                rmax = fmaxf(rmax, __shfl_xor_sync(~0u, rmax, 1));
                rmax = fmaxf(rmax, __shfl_xor_sync(~0u, rmax, 2));
                float mnew = fmaxf(m[si], rmax);
                float sc = __expf(m[si] - mnew);
                float rs = 0.f;
                #pragma unroll
                for (int ni = 0; ni < 4; ni++) {
                    float p0 = __expf(s[mi][ni][rr * 2]     - mnew);
                    float p1 = __expf(s[mi][ni][rr * 2 + 1] - mnew);
                    s[mi][ni][rr * 2]     = p0;
                    s[mi][ni][rr * 2 + 1] = p1;
                    rs += p0 + p1;
                }
                rs += __shfl_xor_sync(~0u, rs, 1);
                rs += __shfl_xor_sync(~0u, rs, 2);
                l[si] = l[si] * sc + rs;
                m[si] = mnew;
                scl[si] = sc;
            }
        }

        // Rescale O
        #pragma unroll
        for (int mi = 0; mi < 2; mi++)
            #pragma unroll
            for (int ni = 0; ni < 8; ni++)
                #pragma unroll
                for (int rr = 0; rr < 2; rr++) {
                    O[mi][ni][rr * 2]     *= scl[mi * 2 + rr];
                    O[mi][ni][rr * 2 + 1] *= scl[mi * 2 + rr];
                }

        // Write P (tf32) to warp-private SMEM rows; warp-local hazard only.
        #pragma unroll
        for (int mi = 0; mi < 2; mi++)
            #pragma unroll
            for (int rr = 0; rr < 2; rr++) {
                int row = wm + mi * 16 + rr * 8 + g;
                #pragma unroll
                for (int ni = 0; ni < 4; ni++) {
                    uint2 t = { to_tf32(s[mi][ni][rr * 2]),
                                to_tf32(s[mi][ni][rr * 2 + 1]) };
                    *(uint2*)&Ps[row * LDP + ni * 8 + tig * 2] = t;
                }
            }
    __syncwarp();

        // O += P @ V   (k = 32 kv positions, n = 64)
        #pragma unroll
        for (int ks = 0; ks < 4; ks++) {
            uint32_t a[2][4], b[8][2];
            #pragma unroll
            for (int mi = 0; mi < 2; mi++) {
                int base = (wm + mi * 16 + g) * LDP + ks * 8 + tig;
                a[mi][0] = Ps[base];
                a[mi][1] = Ps[base + 8 * LDP];
                a[mi][2] = Ps[base + 4];
                a[mi][3] = Ps[base + 8 * LDP + 4];
            }
            #pragma unroll
            for (int ni = 0; ni < 8; ni++) {
                b[ni][0] = Vs[(ks * 8 + tig) * LDV + ni * 8 + g];
                b[ni][1] = Vs[(ks * 8 + tig + 4) * LDV + ni * 8 + g];
            }
            #pragma unroll
            for (int mi = 0; mi < 2; mi++)
                #pragma unroll
                for (int ni = 0; ni < 8; ni++)
                    mma8(O[mi][ni], a[mi], b[ni]);
        }
        __syncwarp();   // Ps reads done before next iteration's warp-local write
    }

    // Epilogue: O / l -> g_C in [B, N, H*64] layout
    #pragma unroll
    for (int mi = 0; mi < 2; mi++)
        #pragma unroll
        for (int rr = 0; rr < 2; rr++) {
            float inv = 1.0f / l[mi * 2 + rr];
            int nn = q0 + wm + mi * 16 + rr * 8 + g;
            #pragma unroll
            for (int ni = 0; ni < 8; ni++) {
                int col = ni * 8 + tig * 2;
                float2 v = { O[mi][ni][rr * 2] * inv,
                             O[mi][ni][rr * 2 + 1] * inv };
                *(float2*)&g_C[((size_t)(bb * SEQ + nn)) * EMB + h * HD + col] = v;
            }
        }
}

// ---------------------------------------------------------------------------
// Kernel 3: out = ctx @ W_proj + b_proj (NN, tf32 MMA).
// ---------------------------------------------------------------------------
__global__ void __launch_bounds__(128) proj_kernel(
    const float* __restrict__ Wp, const float* __restrict__ bp,
    float* __restrict__ out)
{
    __shared__ uint32_t As[128 * LDA_S];
    __shared__ uint32_t Bs[32 * LDB_S];

    const int tid = threadIdx.x;
    const int w = tid >> 5, lane = tid & 31;
    const int g = lane >> 2, tig = lane & 3;
    const int wm = (w >> 1) * 64, wn = (w & 1) * 64;
    const int m0 = blockIdx.x * 128, n0 = blockIdx.y * 128;

    float acc[4][8][4];
    #pragma unroll
    for (int i = 0; i < 4; i++)
        #pragma unroll
        for (int j = 0; j < 8; j++)
            #pragma unroll
            for (int r = 0; r < 4; r++) acc[i][j][r] = 0.f;

    for (int kt = 0; kt < EMB; kt += 32) {
        #pragma unroll
        for (int p = 0; p < 8; p++) {
            int lin = p * 128 + tid;
            int r = lin >> 3, k4 = (lin & 7) << 2;
            float4 v = *(const float4*)&g_C[(size_t)(m0 + r) * EMB + kt + k4];
            uint4 t = { to_tf32(v.x), to_tf32(v.y), to_tf32(v.z), to_tf32(v.w) };
            *(uint4*)&As[r * LDA_S + k4] = t;
        }
        #pragma unroll
        for (int p = 0; p < 8; p++) {
            int lin = p * 128 + tid;
            int r = lin >> 5, c4 = (lin & 31) << 2;
            float4 v = *(const float4*)&Wp[(size_t)(kt + r) * EMB + n0 + c4];
            uint4 t = { to_tf32(v.x), to_tf32(v.y), to_tf32(v.z), to_tf32(v.w) };
            *(uint4*)&Bs[r * LDB_S + c4] = t;
        }
        __syncthreads();
        #pragma unroll
        for (int ks = 0; ks < 4; ks++) {
            uint32_t a[4][4], b[8][2];
            #pragma unroll
            for (int mi = 0; mi < 4; mi++) {
                int base = (wm + mi * 16 + g) * LDA_S + ks * 8 + tig;
                a[mi][0] = As[base];
                a[mi][1] = As[base + 8 * LDA_S];
                a[mi][2] = As[base + 4];
                a[mi][3] = As[base + 8 * LDA_S + 4];
            }
            #pragma unroll
            for (int ni = 0; ni < 8; ni++) {
                int col = wn + ni * 8 + g;
                b[ni][0] = Bs[(ks * 8 + tig) * LDB_S + col];
                b[ni][1] = Bs[(ks * 8 + tig + 4) * LDB_S + col];
            }
            #pragma unroll
            for (int mi = 0; mi < 4; mi++)
                #pragma unroll
                for (int ni = 0; ni < 8; ni++)
                    mma8(acc[mi][ni], a[mi], b[ni]);
        }
        __syncthreads();
    }

    #pragma unroll
    for (int mi = 0; mi < 4; mi++)
        #pragma unroll
        for (int rr = 0; rr < 2; rr++) {
            int gm = m0 + wm + mi * 16 + g + rr * 8;
            #pragma unroll
            for (int ni = 0; ni < 8; ni++) {
                int c = n0 + wn + ni * 8 + tig * 2;
                float2 v = { acc[mi][ni][rr * 2] + bp[c],
                             acc[mi][ni][rr * 2 + 1] + bp[c + 1] };
                *(float2*)&out[(size_t)gm * EMB + c] = v;
            }
        }
}

// ---------------------------------------------------------------------------
extern "C" void kernel_launch(void* const* d_in, const int* in_sizes, int n_in,
                              void* d_out, int out_size)
{
    const float* x   = (const float*)d_in[0];
    const float* Wqk = (const float*)d_in[1];
    const float* bqk = (const float*)d_in[2];
    const float* Wv  = (const float*)d_in[3];
    const float* bv  = (const float*)d_in[4];
    const float* Wp  = (const float*)d_in[5];
    const float* bp  = (const float*)d_in[6];
    float* out = (float*)d_out;

    dim3 g1(MTOT / 128, 18);
    qkv_kernel<<<g1, 128>>>(x, Wqk, bqk, Wv, bv);

    dim3 g2(SEQ / 128, BH);
    flash_kernel<<<g2, 128>>>();

    dim3 g4(MTOT / 128, EMB / 128);
    proj_kernel<<<g4, 128>>>(Wp, bp, out);
}

// round 10
// speedup vs baseline: 3.2775x; 1.1225x over previous
#include <cuda_runtime.h>
#include <cuda_bf16.h>
#include <cstdint>

// Problem constants
#define BATCH 16
#define SEQ   1024
#define EMB   768
#define NH    12
#define HD    64
#define BH    (BATCH*NH)  // 192
#define MTOT  (BATCH*SEQ) // 16384

// Scratch (allocation-free: __device__ globals)
__device__ float g_Q[(size_t)BH*SEQ*HD];
__device__ float g_K[(size_t)BH*SEQ*HD];
__device__ float g_V[(size_t)BH*SEQ*HD];
__device__ float g_C[(size_t)MTOT*EMB];

// ---------------------------------------------------------------------------
// tf32 helpers
// ---------------------------------------------------------------------------
__device__ __forceinline__ uint32_t to_tf32(float f) {
    uint32_t u;
    asm("cvt.rna.tf32.f32 %0, %1;" : "=r"(u) : "f"(f));
    return u;
}

__device__ __forceinline__ void mma8(float* c, const uint32_t* a, const uint32_t* b) {
    asm volatile(
        "mma.sync.aligned.m16n8k8.row.col.f32.tf32.tf32.f32 "
        "{%0,%1,%2,%3},{%4,%5,%6,%7},{%8,%9},{%0,%1,%2,%3};"
        : "+f"(c[0]), "+f"(c[1]), "+f"(c[2]), "+f"(c[3])
        : "r"(a[0]), "r"(a[1]), "r"(a[2]), "r"(a[3]), "r"(b[0]), "r"(b[1]));
}

// SMEM strides
#define LDA_S 36     // GEMM A tile [128][36] (m-major, k inner), stride%32==4
#define LDB_S 136    // GEMM NN B tile [32][136], stride%32==8

// Flash strides
#define LDK 68       // K tile [32][68], %32==4 -> conflict-free NT B-frag
#define LDV 72       // V tile [32][72], %32==8 -> conflict-free NN B-frag
#define LDP 36       // P tile [128][36], %32==4 -> conflict-free A-frag

// ---------------------------------------------------------------------------
// Kernel 1: fused QKV projection (tf32 MMA), software-pipelined.
// 256 threads = 8 warps (4x2), warp tile 32x64, block tile 128x128, BK=32.
// Next K-tile prefetched into registers while MMAs consume current SMEM.
// ---------------------------------------------------------------------------
__global__ void __launch_bounds__(256) qkv_kernel(
    const float* __restrict__ x,
    const float* __restrict__ Wqk, const float* __restrict__ bqk,
    const float* __restrict__ Wv,  const float* __restrict__ bv)
{
    const int bn  = blockIdx.y;
    const bool isV = (bn >= 12);
    const float* Bmat = isV ? Wv : Wqk;
    const int ldb     = isV ? 768 : 1536;
    const int n0      = isV ? (bn - 12) * 128 : bn * 128;
    const float* bias = isV ? bv : bqk;
    const int m0 = blockIdx.x * 128;

    __shared__ uint32_t As[128 * LDA_S];
    __shared__ uint32_t Bs[32 * LDB_S];

    const int tid = threadIdx.x;
    const int w = tid >> 5, lane = tid & 31;
    const int g = lane >> 2, tig = lane & 3;
    const int wm = (w >> 1) * 32, wn = (w & 1) * 64;

    // Per-thread staging coords (A: 4 float4, B: 4 float4)
    const int arow = tid >> 3,  ak4 = (tid & 7) << 2;     // +32 rows per p
    const int brow = tid >> 6,  bc4 = (tid & 63) << 1;    // hmm—use original mapping

    float acc[2][8][4];
    #pragma unroll
    for (int i = 0; i < 2; i++)
        #pragma unroll
        for (int j = 0; j < 8; j++)
            #pragma unroll
            for (int r = 0; r < 4; r++) acc[i][j][r] = 0.f;

    float4 ra[4], rb[4];
    // Preload tile kt=0
    #pragma unroll
    for (int p = 0; p < 4; p++) {
        int lin = p * 256 + tid;
        int r = lin >> 3, k4 = (lin & 7) << 2;
        ra[p] = *(const float4*)&x[(size_t)(m0 + r) * EMB + k4];
    }
    #pragma unroll
    for (int p = 0; p < 4; p++) {
        int lin = p * 256 + tid;
        int r = lin >> 5, c4 = (lin & 31) << 2;
        rb[p] = *(const float4*)&Bmat[(size_t)r * ldb + n0 + c4];
    }

    for (int kt = 0; kt < EMB; kt += 32) {
        // Store staged tile to SMEM (with tf32 cvt)
        #pragma unroll
        for (int p = 0; p < 4; p++) {
            int lin = p * 256 + tid;
            int r = lin >> 3, k4 = (lin & 7) << 2;
            uint4 t = { to_tf32(ra[p].x), to_tf32(ra[p].y),
                        to_tf32(ra[p].z), to_tf32(ra[p].w) };
            *(uint4*)&As[r * LDA_S + k4] = t;
        }
        #pragma unroll
        for (int p = 0; p < 4; p++) {
            int lin = p * 256 + tid;
            int r = lin >> 5, c4 = (lin & 31) << 2;
            uint4 t = { to_tf32(rb[p].x), to_tf32(rb[p].y),
                        to_tf32(rb[p].z), to_tf32(rb[p].w) };
            *(uint4*)&Bs[r * LDB_S + c4] = t;
        }
        __syncthreads();

        // Issue next tile's global loads (latency hidden behind MMAs)
        if (kt + 32 < EMB) {
            #pragma unroll
            for (int p = 0; p < 4; p++) {
                int lin = p * 256 + tid;
                int r = lin >> 3, k4 = (lin & 7) << 2;
                ra[p] = *(const float4*)&x[(size_t)(m0 + r) * EMB + kt + 32 + k4];
            }
            #pragma unroll
            for (int p = 0; p < 4; p++) {
                int lin = p * 256 + tid;
                int r = lin >> 5, c4 = (lin & 31) << 2;
                rb[p] = *(const float4*)&Bmat[(size_t)(kt + 32 + r) * ldb + n0 + c4];
            }
        }

        #pragma unroll
        for (int ks = 0; ks < 4; ks++) {
            uint32_t a[2][4], b[8][2];
            #pragma unroll
            for (int mi = 0; mi < 2; mi++) {
                int base = (wm + mi * 16 + g) * LDA_S + ks * 8 + tig;
                a[mi][0] = As[base];
                a[mi][1] = As[base + 8 * LDA_S];
                a[mi][2] = As[base + 4];
                a[mi][3] = As[base + 8 * LDA_S + 4];
            }
            #pragma unroll
            for (int ni = 0; ni < 8; ni++) {
                int col = wn + ni * 8 + g;
                b[ni][0] = Bs[(ks * 8 + tig) * LDB_S + col];
                b[ni][1] = Bs[(ks * 8 + tig + 4) * LDB_S + col];
            }
            #pragma unroll
            for (int mi = 0; mi < 2; mi++)
                #pragma unroll
                for (int ni = 0; ni < 8; ni++)
                    mma8(acc[mi][ni], a[mi], b[ni]);
        }
        __syncthreads();
    }

    // Epilogue: bias + scatter (Q/K interleaved or V)
    #pragma unroll
    for (int mi = 0; mi < 2; mi++) {
        #pragma unroll
        for (int rr = 0; rr < 2; rr++) {
            int gm = m0 + wm + mi * 16 + g + rr * 8;
            int bb = gm >> 10, nn = gm & 1023;
            #pragma unroll
            for (int ni = 0; ni < 8; ni++) {
                #pragma unroll
                for (int cc = 0; cc < 2; cc++) {
                    int c = n0 + wn + ni * 8 + tig * 2 + cc;
                    float val = acc[mi][ni][rr * 2 + cc] + bias[c];
                    if (isV) {
                        int h = c >> 6, dv = c & 63;
                        g_V[(((size_t)(bb * NH + h)) * SEQ + nn) * HD + dv] = val;
                    } else {
                        int h = c >> 7, rem = c & 127;
                        int di = rem >> 1;
                        size_t idx = (((size_t)(bb * NH + h)) * SEQ + nn) * HD + di;
                        if (rem & 1) g_K[idx] = val; else g_Q[idx] = val;
                    }
                }
            }
        }
    }
}

// ---------------------------------------------------------------------------
// Kernel 2: fused flash attention (static smem 35.5KB), K/V prefetched into
// registers one kv-tile ahead; loads issued right after S-MMA so their
// latency hides behind softmax + P@V.
// ---------------------------------------------------------------------------
__global__ void __launch_bounds__(128) flash_kernel()
{
    __shared__ uint32_t Ks[32 * LDK];
    __shared__ uint32_t Vs[32 * LDV];
    __shared__ uint32_t Ps[128 * LDP];

    const int bh = blockIdx.y;
    const int bb = bh / NH, h = bh % NH;
    const int q0 = blockIdx.x * 128;
    const float* Qg = g_Q + (size_t)bh * SEQ * HD;
    const float* Kg = g_K + (size_t)bh * SEQ * HD;
    const float* Vg = g_V + (size_t)bh * SEQ * HD;

    const int tid = threadIdx.x;
    const int w = tid >> 5, lane = tid & 31;
    const int g = lane >> 2, tig = lane & 3;
    const int wm = w * 32;

    // --- Load Q fragments into registers (scale 1/8 folded in). ---
    uint32_t qa[2][8][4];   // [mi][ks][reg]
    #pragma unroll
    for (int half = 0; half < 2; half++) {
        #pragma unroll
        for (int p = 0; p < 8; p++) {
            int lin = p * 128 + tid;
            int r = lin >> 3, c4 = (lin & 7) << 2;
            float4 v = *(const float4*)&Qg[(size_t)(q0 + r) * HD + half * 32 + c4];
            uint4 t = { to_tf32(v.x * 0.125f), to_tf32(v.y * 0.125f),
                        to_tf32(v.z * 0.125f), to_tf32(v.w * 0.125f) };
            *(uint4*)&Ps[r * LDP + c4] = t;
        }
        __syncthreads();
        #pragma unroll
        for (int ksl = 0; ksl < 4; ksl++) {
            #pragma unroll
            for (int mi = 0; mi < 2; mi++) {
                int base = (wm + mi * 16 + g) * LDP + ksl * 8 + tig;
                qa[mi][half * 4 + ksl][0] = Ps[base];
                qa[mi][half * 4 + ksl][1] = Ps[base + 8 * LDP];
                qa[mi][half * 4 + ksl][2] = Ps[base + 4];
                qa[mi][half * 4 + ksl][3] = Ps[base + 8 * LDP + 4];
            }
        }
        __syncthreads();
    }

    float O[2][8][4];
    #pragma unroll
    for (int mi = 0; mi < 2; mi++)
        #pragma unroll
        for (int ni = 0; ni < 8; ni++)
            #pragma unroll
            for (int r = 0; r < 4; r++) O[mi][ni][r] = 0.f;
    float m[4] = { -1e30f, -1e30f, -1e30f, -1e30f };
    float l[4] = { 0.f, 0.f, 0.f, 0.f };

    // Preload K/V tile 0 into registers
    float4 rk[4], rv[4];
    #pragma unroll
    for (int p = 0; p < 4; p++) {
        int lin = p * 128 + tid;
        int r = lin >> 4, c4 = (lin & 15) << 2;
        rk[p] = *(const float4*)&Kg[(size_t)r * HD + c4];
        rv[p] = *(const float4*)&Vg[(size_t)r * HD + c4];
    }

    for (int kt = 0; kt < SEQ; kt += 32) {
        __syncthreads();   // all reads of Ks/Vs/Ps from prior iteration done
        // Store staged K/V to SMEM (tf32 cvt)
        #pragma unroll
        for (int p = 0; p < 4; p++) {
            int lin = p * 128 + tid;
            int r = lin >> 4, c4 = (lin & 15) << 2;
            uint4 tk = { to_tf32(rk[p].x), to_tf32(rk[p].y),
                         to_tf32(rk[p].z), to_tf32(rk[p].w) };
            *(uint4*)&Ks[r * LDK + c4] = tk;
            uint4 tv = { to_tf32(rv[p].x), to_tf32(rv[p].y),
                         to_tf32(rv[p].z), to_tf32(rv[p].w) };
            *(uint4*)&Vs[r * LDV + c4] = tv;
        }
        __syncthreads();

        // S = Q@K^T (32x32 per warp), k = 64
        float s[2][4][4];
        #pragma unroll
        for (int mi = 0; mi < 2; mi++)
            #pragma unroll
            for (int ni = 0; ni < 4; ni++)
                #pragma unroll
                for (int r = 0; r < 4; r++) s[mi][ni][r] = 0.f;

        #pragma unroll
        for (int ks = 0; ks < 8; ks++) {
            uint32_t b[4][2];
            #pragma unroll
            for (int ni = 0; ni < 4; ni++) {
                int base = (ni * 8 + g) * LDK + ks * 8 + tig;
                b[ni][0] = Ks[base];
                b[ni][1] = Ks[base + 4];
            }
            #pragma unroll
            for (int mi = 0; mi < 2; mi++)
                #pragma unroll
                for (int ni = 0; ni < 4; ni++)
                    mma8(s[mi][ni], qa[mi][ks], b[ni]);
        }

        // Issue next K/V tile loads (latency hidden behind softmax + PV mma)
        if (kt + 32 < SEQ) {
            #pragma unroll
            for (int p = 0; p < 4; p++) {
                int lin = p * 128 + tid;
                int r = lin >> 4, c4 = (lin & 15) << 2;
                rk[p] = *(const float4*)&Kg[(size_t)(kt + 32 + r) * HD + c4];
                rv[p] = *(const float4*)&Vg[(size_t)(kt + 32 + r) * HD + c4];
            }
        }

        // Online softmax update (rows in-warp: reduce over tig lanes only)
        float scl[4];
        #pragma unroll
        for (int mi = 0; mi < 2; mi++) {
            #pragma unroll
            for (int rr = 0; rr < 2; rr++) {
                int si = mi * 2 + rr;
                float rmax = -1e30f;
                #pragma unroll
                for (int ni = 0; ni < 4; ni++) {
                    rmax = fmaxf(rmax, s[mi][ni][rr * 2]);
                    rmax = fmaxf(rmax, s[mi][ni][rr * 2 + 1]);
                }
                rmax = fmaxf(rmax, __shfl_xor_sync(~0u, rmax, 1));
                rmax = fmaxf(rmax, __shfl_xor_sync(~0u, rmax, 2));
                float mnew = fmaxf(m[si], rmax);
                float sc = __expf(m[si] - mnew);
                float rs = 0.f;
                #pragma unroll
                for (int ni = 0; ni < 4; ni++) {
                    float p0 = __expf(s[mi][ni][rr * 2]     - mnew);
                    float p1 = __expf(s[mi][ni][rr * 2 + 1] - mnew);
                    s[mi][ni][rr * 2]     = p0;
                    s[mi][ni][rr * 2 + 1] = p1;
                    rs += p0 + p1;
                }
                rs += __shfl_xor_sync(~0u, rs, 1);
                rs += __shfl_xor_sync(~0u, rs, 2);
                l[si] = l[si] * sc + rs;
                m[si] = mnew;
                scl[si] = sc;
            }
        }

        // Rescale O
        #pragma unroll
        for (int mi = 0; mi < 2; mi++)
            #pragma unroll
            for (int ni = 0; ni < 8; ni++)
                #pragma unroll
                for (int rr = 0; rr < 2; rr++) {
                    O[mi][ni][rr * 2]     *= scl[mi * 2 + rr];
                    O[mi][ni][rr * 2 + 1] *= scl[mi * 2 + rr];
                }

        // Write P (tf32) to warp-private SMEM rows; warp-local hazard only.
        #pragma unroll
        for (int mi = 0; mi < 2; mi++)
            #pragma unroll
            for (int rr = 0; rr < 2; rr++) {
                int row = wm + mi * 16 + rr * 8 + g;
                #pragma unroll
                for (int ni = 0; ni < 4; ni++) {
                    uint2 t = { to_tf32(s[mi][ni][rr * 2]),
                                to_tf32(s[mi][ni][rr * 2 + 1]) };
                    *(uint2*)&Ps[row * LDP + ni * 8 + tig * 2] = t;
                }
            }
        __syncwarp();

        // O += P @ V   (k = 32 kv positions, n = 64)
        #pragma unroll
        for (int ks = 0; ks < 4; ks++) {
            uint32_t a[2][4], b[8][2];
            #pragma unroll
            for (int mi = 0; mi < 2; mi++) {
                int base = (wm + mi * 16 + g) * LDP + ks * 8 + tig;
                a[mi][0] = Ps[base];
                a[mi][1] = Ps[base + 8 * LDP];
                a[mi][2] = Ps[base + 4];
                a[mi][3] = Ps[base + 8 * LDP + 4];
            }
            #pragma unroll
            for (int ni = 0; ni < 8; ni++) {
                b[ni][0] = Vs[(ks * 8 + tig) * LDV + ni * 8 + g];
                b[ni][1] = Vs[(ks * 8 + tig + 4) * LDV + ni * 8 + g];
            }
            #pragma unroll
            for (int mi = 0; mi < 2; mi++)
                #pragma unroll
                for (int ni = 0; ni < 8; ni++)
                    mma8(O[mi][ni], a[mi], b[ni]);
        }
        __syncwarp();   // Ps reads done before next iteration's warp-local write
    }

    // Epilogue: O / l -> g_C in [B, N, H*64] layout
    #pragma unroll
    for (int mi = 0; mi < 2; mi++)
        #pragma unroll
        for (int rr = 0; rr < 2; rr++) {
            float inv = 1.0f / l[mi * 2 + rr];
            int nn = q0 + wm + mi * 16 + rr * 8 + g;
            #pragma unroll
            for (int ni = 0; ni < 8; ni++) {
                int col = ni * 8 + tig * 2;
                float2 v = { O[mi][ni][rr * 2] * inv,
                             O[mi][ni][rr * 2 + 1] * inv };
                *(float2*)&g_C[((size_t)(bb * SEQ + nn)) * EMB + h * HD + col] = v;
            }
        }
}

// ---------------------------------------------------------------------------
// Kernel 3: out = ctx @ W_proj + b_proj (NN, tf32 MMA), software-pipelined.
// 256 threads, warp tile 32x64.
// ---------------------------------------------------------------------------
__global__ void __launch_bounds__(256) proj_kernel(
    const float* __restrict__ Wp, const float* __restrict__ bp,
    float* __restrict__ out)
{
    __shared__ uint32_t As[128 * LDA_S];
    __shared__ uint32_t Bs[32 * LDB_S];

    const int tid = threadIdx.x;
    const int w = tid >> 5, lane = tid & 31;
    const int g = lane >> 2, tig = lane & 3;
    const int wm = (w >> 1) * 32, wn = (w & 1) * 64;
    const int m0 = blockIdx.x * 128, n0 = blockIdx.y * 128;

    float acc[2][8][4];
    #pragma unroll
    for (int i = 0; i < 2; i++)
        #pragma unroll
        for (int j = 0; j < 8; j++)
            #pragma unroll
            for (int r = 0; r < 4; r++) acc[i][j][r] = 0.f;

    float4 ra[4], rb[4];
    #pragma unroll
    for (int p = 0; p < 4; p++) {
        int lin = p * 256 + tid;
        int r = lin >> 3, k4 = (lin & 7) << 2;
        ra[p] = *(const float4*)&g_C[(size_t)(m0 + r) * EMB + k4];
    }
    #pragma unroll
    for (int p = 0; p < 4; p++) {
        int lin = p * 256 + tid;
        int r = lin >> 5, c4 = (lin & 31) << 2;
        rb[p] = *(const float4*)&Wp[(size_t)r * EMB + n0 + c4];
    }

    for (int kt = 0; kt < EMB; kt += 32) {
        #pragma unroll
        for (int p = 0; p < 4; p++) {
            int lin = p * 256 + tid;
            int r = lin >> 3, k4 = (lin & 7) << 2;
            uint4 t = { to_tf32(ra[p].x), to_tf32(ra[p].y),
                        to_tf32(ra[p].z), to_tf32(ra[p].w) };
            *(uint4*)&As[r * LDA_S + k4] = t;
        }
        #pragma unroll
        for (int p = 0; p < 4; p++) {
            int lin = p * 256 + tid;
            int r = lin >> 5, c4 = (lin & 31) << 2;
            uint4 t = { to_tf32(rb[p].x), to_tf32(rb[p].y),
                        to_tf32(rb[p].z), to_tf32(rb[p].w) };
            *(uint4*)&Bs[r * LDB_S + c4] = t;
        }
        __syncthreads();

        if (kt + 32 < EMB) {
            #pragma unroll
            for (int p = 0; p < 4; p++) {
                int lin = p * 256 + tid;
                int r = lin >> 3, k4 = (lin & 7) << 2;
                ra[p] = *(const float4*)&g_C[(size_t)(m0 + r) * EMB + kt + 32 + k4];
            }
            #pragma unroll
            for (int p = 0; p < 4; p++) {
                int lin = p * 256 + tid;
                int r = lin >> 5, c4 = (lin & 31) << 2;
                rb[p] = *(const float4*)&Wp[(size_t)(kt + 32 + r) * EMB + n0 + c4];
            }
        }

        #pragma unroll
        for (int ks = 0; ks < 4; ks++) {
            uint32_t a[2][4], b[8][2];
            #pragma unroll
            for (int mi = 0; mi < 2; mi++) {
                int base = (wm + mi * 16 + g) * LDA_S + ks * 8 + tig;
                a[mi][0] = As[base];
                a[mi][1] = As[base + 8 * LDA_S];
                a[mi][2] = As[base + 4];
                a[mi][3] = As[base + 8 * LDA_S + 4];
            }
            #pragma unroll
            for (int ni = 0; ni < 8; ni++) {
                int col = wn + ni * 8 + g;
                b[ni][0] = Bs[(ks * 8 + tig) * LDB_S + col];
                b[ni][1] = Bs[(ks * 8 + tig + 4) * LDB_S + col];
            }
            #pragma unroll
            for (int mi = 0; mi < 2; mi++)
                #pragma unroll
                for (int ni = 0; ni < 8; ni++)
                    mma8(acc[mi][ni], a[mi], b[ni]);
        }
        __syncthreads();
    }

    #pragma unroll
    for (int mi = 0; mi < 2; mi++)
        #pragma unroll
        for (int rr = 0; rr < 2; rr++) {
            int gm = m0 + wm + mi * 16 + g + rr * 8;
            #pragma unroll
            for (int ni = 0; ni < 8; ni++) {
                int c = n0 + wn + ni * 8 + tig * 2;
                float2 v = { acc[mi][ni][rr * 2] + bp[c],
                             acc[mi][ni][rr * 2 + 1] + bp[c + 1] };
                *(float2*)&out[(size_t)gm * EMB + c] = v;
            }
        }
}

// ---------------------------------------------------------------------------
extern "C" void kernel_launch(void* const* d_in, const int* in_sizes, int n_in,
                              void* d_out, int out_size)
{
    const float* x   = (const float*)d_in[0];
    const float* Wqk = (const float*)d_in[1];
    const float* bqk = (const float*)d_in[2];
    const float* Wv  = (const float*)d_in[3];
    const float* bv  = (const float*)d_in[4];
    const float* Wp  = (const float*)d_in[5];
    const float* bp  = (const float*)d_in[6];
    float* out = (float*)d_out;

    dim3 g1(MTOT / 128, 18);
    qkv_kernel<<<g1, 256>>>(x, Wqk, bqk, Wv, bv);

    dim3 g2(SEQ / 128, BH);
    flash_kernel<<<g2, 128>>>();

    dim3 g4(MTOT / 128, EMB / 128);
    proj_kernel<<<g4, 256>>>(Wp, bp, out);
}

// round 12
// speedup vs baseline: 3.6024x; 1.0991x over previous
#include <cuda_runtime.h>
#include <cuda_bf16.h>
#include <cstdint>

// Problem constants
#define BATCH 16
#define SEQ   1024
#define EMB   768
#define NH    12
#define HD    64
#define BH    (BATCH*NH)  // 192
#define MTOT  (BATCH*SEQ) // 16384

// Scratch (allocation-free: __device__ globals)
__device__ float g_Q[(size_t)BH*SEQ*HD];
__device__ float g_K[(size_t)BH*SEQ*HD];
__device__ float g_V[(size_t)BH*SEQ*HD];
__device__ float g_C[(size_t)MTOT*EMB];
// tf32-pre-rounded copies of inputs
__device__ float g_X[(size_t)MTOT*EMB];
__device__ float g_Wqk[(size_t)EMB*2*EMB];
__device__ float g_Wv[(size_t)EMB*EMB];
__device__ float g_Wp[(size_t)EMB*EMB];

// ---------------------------------------------------------------------------
// tf32 + cp.async helpers
// ---------------------------------------------------------------------------
__device__ __forceinline__ uint32_t to_tf32(float f) {
    uint32_t u;
    asm("cvt.rna.tf32.f32 %0, %1;" : "=r"(u) : "f"(f));
    return u;
}

__device__ __forceinline__ void mma8(float* c, const uint32_t* a, const uint32_t* b) {
    asm volatile(
        "mma.sync.aligned.m16n8k8.row.col.f32.tf32.tf32.f32 "
        "{%0,%1,%2,%3},{%4,%5,%6,%7},{%8,%9},{%0,%1,%2,%3};"
        : "+f"(c[0]), "+f"(c[1]), "+f"(c[2]), "+f"(c[3])
        : "r"(a[0]), "r"(a[1]), "r"(a[2]), "r"(a[3]), "r"(b[0]), "r"(b[1]));
}

__device__ __forceinline__ void cp16(uint32_t smem, const void* g) {
    asm volatile("cp.async.cg.shared.global [%0], [%1], 16;\n" :: "r"(smem), "l"(g));
}
__device__ __forceinline__ void cp_commit() {
    asm volatile("cp.async.commit_group;\n");
}
__device__ __forceinline__ void cp_wait1() {
    asm volatile("cp.async.wait_group 1;\n");
}
__device__ __forceinline__ void cp_wait0() {
    asm volatile("cp.async.wait_group 0;\n");
}

// SMEM strides
#define LDA_S 20     // A tile [128][20] (m-major, k inner, BK=16); 20%32: frag banks 20g+tig all-distinct
#define LDB_S 136    // B tile [16][136] (k-major, n inner), %32==8 -> 8tig+g distinct

// Flash strides
#define LDK 68
#define LDV 72
#define LDP 36

// ---------------------------------------------------------------------------
// Kernel 0: round fp32 -> tf32-representable fp32 (vectorized).
// ---------------------------------------------------------------------------
__global__ void __launch_bounds__(256) round_kernel(
    const float* __restrict__ in, float* __restrict__ out, int n4)
{
    int i = blockIdx.x * 256 + threadIdx.x;
    if (i < n4) {
        float4 v = *(const float4*)&in[(size_t)i * 4];
        uint4 t = { to_tf32(v.x), to_tf32(v.y), to_tf32(v.z), to_tf32(v.w) };
        *(uint4*)&out[(size_t)i * 4] = t;
    }
}

// ---------------------------------------------------------------------------
// Kernel 1: fused QKV projection. cp.async 2-stage double buffer, BK=16.
// 256 threads = 8 warps (4x2), warp tile 32x64, block tile 128x128.
// Inputs pre-rounded -> no cvt in mainloop, no staging regs.
// ---------------------------------------------------------------------------
__global__ void __launch_bounds__(256, 2) qkv_kernel(
    const float* __restrict__ bqk, const float* __restrict__ bv)
{
    const int bn  = blockIdx.y;
    const bool isV = (bn >= 12);
    const float* Bmat = isV ? g_Wv : g_Wqk;
    const int ldb     = isV ? 768 : 1536;
    const int n0      = isV ? (bn - 12) * 128 : bn * 128;
    const float* bias = isV ? bv : bqk;
    const int m0 = blockIdx.x * 128;

    __shared__ uint32_t As[2][128 * LDA_S];
    __shared__ uint32_t Bs[2][16 * LDB_S];

    const int tid = threadIdx.x;
    const int w = tid >> 5, lane = tid & 31;
    const int g = lane >> 2, tig = lane & 3;
    const int wm = (w >> 1) * 32, wn = (w & 1) * 64;

    // cp.async coords: A 128x16 = 512 float4 (2/thread); B 16x128 = 512 float4
    const int ar0 = tid >> 2,        ak0 = (tid & 3) << 2;        // p=0
    const int ar1 = (256 + tid) >> 2, ak1 = ((256 + tid) & 3) << 2;
    const int br0 = tid >> 5,        bc0 = (tid & 31) << 2;
    const int br1 = (256 + tid) >> 5, bc1 = ((256 + tid) & 31) << 2;

    uint32_t sA[2][2], sB[2][2];
    #pragma unroll
    for (int s = 0; s < 2; s++) {
        sA[s][0] = (uint32_t)__cvta_generic_to_shared(&As[s][ar0 * LDA_S + ak0]);
        sA[s][1] = (uint32_t)__cvta_generic_to_shared(&As[s][ar1 * LDA_S + ak1]);
        sB[s][0] = (uint32_t)__cvta_generic_to_shared(&Bs[s][br0 * LDB_S + bc0]);
        sB[s][1] = (uint32_t)__cvta_generic_to_shared(&Bs[s][br1 * LDB_S + bc1]);
    }

    float acc[2][8][4];
    #pragma unroll
    for (int i = 0; i < 2; i++)
        #pragma unroll
        for (int j = 0; j < 8; j++)
            #pragma unroll
            for (int r = 0; r < 4; r++) acc[i][j][r] = 0.f;

    // Prologue: issue tile 0 into stage 0
    cp16(sA[0][0], &g_X[(size_t)(m0 + ar0) * EMB + ak0]);
    cp16(sA[0][1], &g_X[(size_t)(m0 + ar1) * EMB + ak1]);
    cp16(sB[0][0], &Bmat[(size_t)br0 * ldb + n0 + bc0]);
    cp16(sB[0][1], &Bmat[(size_t)br1 * ldb + n0 + bc1]);
    cp_commit();

    const int NIT = EMB / 16;   // 48
    for (int it = 0; it < NIT; it++) {
        const int s = it & 1;
        if (it + 1 < NIT) {
            const int kt = (it + 1) * 16;
            const int ns = (it + 1) & 1;
            cp16(sA[ns][0], &g_X[(size_t)(m0 + ar0) * EMB + kt + ak0]);
            cp16(sA[ns][1], &g_X[(size_t)(m0 + ar1) * EMB + kt + ak1]);
            cp16(sB[ns][0], &Bmat[(size_t)(kt + br0) * ldb + n0 + bc0]);
            cp16(sB[ns][1], &Bmat[(size_t)(kt + br1) * ldb + n0 + bc1]);
            cp_commit();
            cp_wait1();
        } else {
            cp_wait0();
        }
        __syncthreads();

        #pragma unroll
        for (int ks = 0; ks < 2; ks++) {
            uint32_t a[2][4], b[8][2];
            #pragma unroll
            for (int mi = 0; mi < 2; mi++) {
                int base = (wm + mi * 16 + g) * LDA_S + ks * 8 + tig;
                a[mi][0] = As[s][base];
                a[mi][1] = As[s][base + 8 * LDA_S];
                a[mi][2] = As[s][base + 4];
                a[mi][3] = As[s][base + 8 * LDA_S + 4];
            }
            #pragma unroll
            for (int ni = 0; ni < 8; ni++) {
                int col = wn + ni * 8 + g;
                b[ni][0] = Bs[s][(ks * 8 + tig) * LDB_S + col];
                b[ni][1] = Bs[s][(ks * 8 + tig + 4) * LDB_S + col];
            }
            #pragma unroll
            for (int mi = 0; mi < 2; mi++)
                #pragma unroll
                for (int ni = 0; ni < 8; ni++)
                    mma8(acc[mi][ni], a[mi], b[ni]);
        }
        __syncthreads();   // everyone done with stage s before it's overwritten
    }

    // Epilogue: bias + scatter, STORED tf32-ROUNDED (flash uses bits directly)
    #pragma unroll
    for (int mi = 0; mi < 2; mi++) {
        #pragma unroll
        for (int rr = 0; rr < 2; rr++) {
            int gm = m0 + wm + mi * 16 + g + rr * 8;
            int bb = gm >> 10, nn = gm & 1023;
            #pragma unroll
            for (int ni = 0; ni < 8; ni++) {
                #pragma unroll
                for (int cc = 0; cc < 2; cc++) {
                    int c = n0 + wn + ni * 8 + tig * 2 + cc;
                    float val = __uint_as_float(to_tf32(acc[mi][ni][rr * 2 + cc] + bias[c]));
                    if (isV) {
                        int h = c >> 6, dv = c & 63;
                        g_V[(((size_t)(bb * NH + h)) * SEQ + nn) * HD + dv] = val;
                    } else {
                        int h = c >> 7, rem = c & 127;
                        int di = rem >> 1;
                        size_t idx = (((size_t)(bb * NH + h)) * SEQ + nn) * HD + di;
                        if (rem & 1) g_K[idx] = val; else g_Q[idx] = val;
                    }
                }
            }
        }
    }
}

// ---------------------------------------------------------------------------
// Kernel 2: fused flash attention. Q/K/V arrive tf32-rounded -> raw bit loads
// (no cvt). K/V register-prefetched one tile ahead. Static smem 35.5KB.
// ---------------------------------------------------------------------------
__global__ void __launch_bounds__(128) flash_kernel()
{
    __shared__ uint32_t Ks[32 * LDK];
    __shared__ uint32_t Vs[32 * LDV];
    __shared__ uint32_t Ps[128 * LDP];

    const int bh = blockIdx.y;
    const int bb = bh / NH, h = bh % NH;
    const int q0 = blockIdx.x * 128;
    const float* Qg = g_Q + (size_t)bh * SEQ * HD;
    const float* Kg = g_K + (size_t)bh * SEQ * HD;
    const float* Vg = g_V + (size_t)bh * SEQ * HD;

    const int tid = threadIdx.x;
    const int w = tid >> 5, lane = tid & 31;
    const int g = lane >> 2, tig = lane & 3;
    const int wm = w * 32;

    // --- Q fragments to registers. g_Q is tf32-rounded; *0.125f is an exact
    // exponent shift so the product is still tf32-representable. ---
    uint32_t qa[2][8][4];
    #pragma unroll
    for (int half = 0; half < 2; half++) {
        #pragma unroll
        for (int p = 0; p < 8; p++) {
            int lin = p * 128 + tid;
            int r = lin >> 3, c4 = (lin & 7) << 2;
            float4 v = *(const float4*)&Qg[(size_t)(q0 + r) * HD + half * 32 + c4];
            uint4 t = { __float_as_uint(v.x * 0.125f), __float_as_uint(v.y * 0.125f),
                        __float_as_uint(v.z * 0.125f), __float_as_uint(v.w * 0.125f) };
            *(uint4*)&Ps[r * LDP + c4] = t;
        }
        __syncthreads();
        #pragma unroll
        for (int ksl = 0; ksl < 4; ksl++) {
            #pragma unroll
            for (int mi = 0; mi < 2; mi++) {
                int base = (wm + mi * 16 + g) * LDP + ksl * 8 + tig;
                qa[mi][half * 4 + ksl][0] = Ps[base];
                qa[mi][half * 4 + ksl][1] = Ps[base + 8 * LDP];
                qa[mi][half * 4 + ksl][2] = Ps[base + 4];
                qa[mi][half * 4 + ksl][3] = Ps[base + 8 * LDP + 4];
            }
        }
        __syncthreads();
    }

    float O[2][8][4];
    #pragma unroll
    for (int mi = 0; mi < 2; mi++)
        #pragma unroll
        for (int ni = 0; ni < 8; ni++)
            #pragma unroll
            for (int r = 0; r < 4; r++) O[mi][ni][r] = 0.f;
    float m[4] = { -1e30f, -1e30f, -1e30f, -1e30f };
    float l[4] = { 0.f, 0.f, 0.f, 0.f };

    // Preload K/V tile 0 (raw bits; already tf32-rounded)
    uint4 rk[4], rv[4];
    #pragma unroll
    for (int p = 0; p < 4; p++) {
        int lin = p * 128 + tid;
        int r = lin >> 4, c4 = (lin & 15) << 2;
        rk[p] = *(const uint4*)&Kg[(size_t)r * HD + c4];
        rv[p] = *(const uint4*)&Vg[(size_t)r * HD + c4];
    }

    for (int kt = 0; kt < SEQ; kt += 32) {
        __syncthreads();
        #pragma unroll
        for (int p = 0; p < 4; p++) {
            int lin = p * 128 + tid;
            int r = lin >> 4, c4 = (lin & 15) << 2;
            *(uint4*)&Ks[r * LDK + c4] = rk[p];
            *(uint4*)&Vs[r * LDV + c4] = rv[p];
        }
        __syncthreads();

        // S = Q@K^T (32x32 per warp), k = 64
        float s[2][4][4];
        #pragma unroll
        for (int mi = 0; mi < 2; mi++)
            #pragma unroll
            for (int ni = 0; ni < 4; ni++)
                #pragma unroll
                for (int r = 0; r < 4; r++) s[mi][ni][r] = 0.f;

        #pragma unroll
        for (int ks = 0; ks < 8; ks++) {
            uint32_t b[4][2];
            #pragma unroll
            for (int ni = 0; ni < 4; ni++) {
                int base = (ni * 8 + g) * LDK + ks * 8 + tig;
                b[ni][0] = Ks[base];
                b[ni][1] = Ks[base + 4];
            }
            #pragma unroll
            for (int mi = 0; mi < 2; mi++)
                #pragma unroll
                for (int ni = 0; ni < 4; ni++)
                    mma8(s[mi][ni], qa[mi][ks], b[ni]);
        }

        // Prefetch next K/V tile (hidden behind softmax + PV mma)
        if (kt + 32 < SEQ) {
            #pragma unroll
            for (int p = 0; p < 4; p++) {
                int lin = p * 128 + tid;
                int r = lin >> 4, c4 = (lin & 15) << 2;
                rk[p] = *(const uint4*)&Kg[(size_t)(kt + 32 + r) * HD + c4];
                rv[p] = *(const uint4*)&Vg[(size_t)(kt + 32 + r) * HD + c4];
            }
        }

        // Online softmax (rows in-warp; reduce over 4 tig lanes)
        float scl[4];
        #pragma unroll
        for (int mi = 0; mi < 2; mi++) {
            #pragma unroll
            for (int rr = 0; rr < 2; rr++) {
                int si = mi * 2 + rr;
                float rmax = -1e30f;
                #pragma unroll
                for (int ni = 0; ni < 4; ni++) {
                    rmax = fmaxf(rmax, s[mi][ni][rr * 2]);
                    rmax = fmaxf(rmax, s[mi][ni][rr * 2 + 1]);
                }
                rmax = fmaxf(rmax, __shfl_xor_sync(~0u, rmax, 1));
                rmax = fmaxf(rmax, __shfl_xor_sync(~0u, rmax, 2));
                float mnew = fmaxf(m[si], rmax);
                float sc = __expf(m[si] - mnew);
                float rs = 0.f;
                #pragma unroll
                for (int ni = 0; ni < 4; ni++) {
                    float p0 = __expf(s[mi][ni][rr * 2]     - mnew);
                    float p1 = __expf(s[mi][ni][rr * 2 + 1] - mnew);
                    s[mi][ni][rr * 2]     = p0;
                    s[mi][ni][rr * 2 + 1] = p1;
                    rs += p0 + p1;
                }
                rs += __shfl_xor_sync(~0u, rs, 1);
                rs += __shfl_xor_sync(~0u, rs, 2);
                l[si] = l[si] * sc + rs;
                m[si] = mnew;
                scl[si] = sc;
            }
        }

        // Rescale O
        #pragma unroll
        for (int mi = 0; mi < 2; mi++)
            #pragma unroll
            for (int ni = 0; ni < 8; ni++)
                #pragma unroll
                for (int rr = 0; rr < 2; rr++) {
                    O[mi][ni][rr * 2]     *= scl[mi * 2 + rr];
                    O[mi][ni][rr * 2 + 1] *= scl[mi * 2 + rr];
                }

        // P (tf32 cvt needed: freshly computed) -> warp-private SMEM rows
        #pragma unroll
        for (int mi = 0; mi < 2; mi++)
            #pragma unroll
            for (int rr = 0; rr < 2; rr++) {
                int row = wm + mi * 16 + rr * 8 + g;
                #pragma unroll
                for (int ni = 0; ni < 4; ni++) {
                    uint2 t = { to_tf32(s[mi][ni][rr * 2]),
                                to_tf32(s[mi][ni][rr * 2 + 1]) };
                    *(uint2*)&Ps[row * LDP + ni * 8 + tig * 2] = t;
                }
            }
        __syncwarp();

        // O += P @ V
        #pragma unroll
        for (int ks = 0; ks < 4; ks++) {
            uint32_t a[2][4], b[8][2];
            #pragma unroll
            for (int mi = 0; mi < 2; mi++) {
                int base = (wm + mi * 16 + g) * LDP + ks * 8 + tig;
                a[mi][0] = Ps[base];
                a[mi][1] = Ps[base + 8 * LDP];
                a[mi][2] = Ps[base + 4];
                a[mi][3] = Ps[base + 8 * LDP + 4];
            }
            #pragma unroll
            for (int ni = 0; ni < 8; ni++) {
                b[ni][0] = Vs[(ks * 8 + tig) * LDV + ni * 8 + g];
                b[ni][1] = Vs[(ks * 8 + tig + 4) * LDV + ni * 8 + g];
            }
            #pragma unroll
            for (int mi = 0; mi < 2; mi++)
                #pragma unroll
                for (int ni = 0; ni < 8; ni++)
                    mma8(O[mi][ni], a[mi], b[ni]);
        }
        __syncwarp();
    }

    // Epilogue: O / l, tf32-rounded so proj reads raw bits
    #pragma unroll
    for (int mi = 0; mi < 2; mi++)
        #pragma unroll
        for (int rr = 0; rr < 2; rr++) {
            float inv = 1.0f / l[mi * 2 + rr];
            int nn = q0 + wm + mi * 16 + rr * 8 + g;
            #pragma unroll
            for (int ni = 0; ni < 8; ni++) {
                int col = ni * 8 + tig * 2;
                uint2 v = { to_tf32(O[mi][ni][rr * 2] * inv),
                            to_tf32(O[mi][ni][rr * 2 + 1] * inv) };
                *(uint2*)&g_C[((size_t)(bb * SEQ + nn)) * EMB + h * HD + col] = v;
            }
        }
}

// ---------------------------------------------------------------------------
// Kernel 3: out = ctx @ W_proj + b_proj. cp.async 2-stage, BK=16.
// ---------------------------------------------------------------------------
__global__ void __launch_bounds__(256, 2) proj_kernel(
    const float* __restrict__ bp, float* __restrict__ out)
{
    __shared__ uint32_t As[2][128 * LDA_S];
    __shared__ uint32_t Bs[2][16 * LDB_S];

    const int tid = threadIdx.x;
    const int w = tid >> 5, lane = tid & 31;
    const int g = lane >> 2, tig = lane & 3;
    const int wm = (w >> 1) * 32, wn = (w & 1) * 64;
    const int m0 = blockIdx.x * 128, n0 = blockIdx.y * 128;

    const int ar0 = tid >> 2,         ak0 = (tid & 3) << 2;
    const int ar1 = (256 + tid) >> 2, ak1 = ((256 + tid) & 3) << 2;
    const int br0 = tid >> 5,         bc0 = (tid & 31) << 2;
    const int br1 = (256 + tid) >> 5, bc1 = ((256 + tid) & 31) << 2;

    uint32_t sA[2][2], sB[2][2];
    #pragma unroll
    for (int s = 0; s < 2; s++) {
        sA[s][0] = (uint32_t)__cvta_generic_to_shared(&As[s][ar0 * LDA_S + ak0]);
        sA[s][1] = (uint32_t)__cvta_generic_to_shared(&As[s][ar1 * LDA_S + ak1]);
        sB[s][0] = (uint32_t)__cvta_generic_to_shared(&Bs[s][br0 * LDB_S + bc0]);
        sB[s][1] = (uint32_t)__cvta_generic_to_shared(&Bs[s][br1 * LDB_S + bc1]);
    }

    float acc[2][8][4];
    #pragma unroll
    for (int i = 0; i < 2; i++)
        #pragma unroll
        for (int j = 0; j < 8; j++)
            #pragma unroll
            for (int r = 0; r < 4; r++) acc[i][j][r] = 0.f;

    cp16(sA[0][0], &g_C[(size_t)(m0 + ar0) * EMB + ak0]);
    cp16(sA[0][1], &g_C[(size_t)(m0 + ar1) * EMB + ak1]);
    cp16(sB[0][0], &g_Wp[(size_t)br0 * EMB + n0 + bc0]);
    cp16(sB[0][1], &g_Wp[(size_t)br1 * EMB + n0 + bc1]);
    cp_commit();

    const int NIT = EMB / 16;
    for (int it = 0; it < NIT; it++) {
        const int s = it & 1;
        if (it + 1 < NIT) {
            const int kt = (it + 1) * 16;
            const int ns = (it + 1) & 1;
            cp16(sA[ns][0], &g_C[(size_t)(m0 + ar0) * EMB + kt + ak0]);
            cp16(sA[ns][1], &g_C[(size_t)(m0 + ar1) * EMB + kt + ak1]);
            cp16(sB[ns][0], &g_Wp[(size_t)(kt + br0) * EMB + n0 + bc0]);
            cp16(sB[ns][1], &g_Wp[(size_t)(kt + br1) * EMB + n0 + bc1]);
            cp_commit();
            cp_wait1();
        } else {
            cp_wait0();
        }
        __syncthreads();

        #pragma unroll
        for (int ks = 0; ks < 2; ks++) {
            uint32_t a[2][4], b[8][2];
            #pragma unroll
            for (int mi = 0; mi < 2; mi++) {
                int base = (wm + mi * 16 + g) * LDA_S + ks * 8 + tig;
                a[mi][0] = As[s][base];
                a[mi][1] = As[s][base + 8 * LDA_S];
                a[mi][2] = As[s][base + 4];
                a[mi][3] = As[s][base + 8 * LDA_S + 4];
            }
            #pragma unroll
            for (int ni = 0; ni < 8; ni++) {
                int col = wn + ni * 8 + g;
                b[ni][0] = Bs[s][(ks * 8 + tig) * LDB_S + col];
                b[ni][1] = Bs[s][(ks * 8 + tig + 4) * LDB_S + col];
            }
            #pragma unroll
            for (int mi = 0; mi < 2; mi++)
                #pragma unroll
                for (int ni = 0; ni < 8; ni++)
                    mma8(acc[mi][ni], a[mi], b[ni]);
        }
        __syncthreads();
    }

    #pragma unroll
    for (int mi = 0; mi < 2; mi++)
        #pragma unroll
        for (int rr = 0; rr < 2; rr++) {
            int gm = m0 + wm + mi * 16 + g + rr * 8;
            #pragma unroll
            for (int ni = 0; ni < 8; ni++) {
                int c = n0 + wn + ni * 8 + tig * 2;
                float2 v = { acc[mi][ni][rr * 2] + bp[c],
                             acc[mi][ni][rr * 2 + 1] + bp[c + 1] };
                *(float2*)&out[(size_t)gm * EMB + c] = v;
            }
        }
}

// ---------------------------------------------------------------------------
extern "C" void kernel_launch(void* const* d_in, const int* in_sizes, int n_in,
                              void* d_out, int out_size)
{
    const float* x   = (const float*)d_in[0];
    const float* Wqk = (const float*)d_in[1];
    const float* bqk = (const float*)d_in[2];
    const float* Wv  = (const float*)d_in[3];
    const float* bv  = (const float*)d_in[4];
    const float* Wp  = (const float*)d_in[5];
    const float* bp  = (const float*)d_in[6];
    float* out = (float*)d_out;

    float *dX, *dWqk, *dWv, *dWp;
    cudaGetSymbolAddress((void**)&dX,   g_X);
    cudaGetSymbolAddress((void**)&dWqk, g_Wqk);
    cudaGetSymbolAddress((void**)&dWv,  g_Wv);
    cudaGetSymbolAddress((void**)&dWp,  g_Wp);

    // Pre-round inputs to tf32-representable fp32 (one rna per value; all
    // downstream kernels consume raw bits -> numerics identical to in-loop cvt)
    {
        int n4;
        n4 = MTOT * EMB / 4;      round_kernel<<<(n4 + 255) / 256, 256>>>(x,   dX,   n4);
        n4 = EMB * 2 * EMB / 4;   round_kernel<<<(n4 + 255) / 256, 256>>>(Wqk, dWqk, n4);
        n4 = EMB * EMB / 4;       round_kernel<<<(n4 + 255) / 256, 256>>>(Wv,  dWv,  n4);
        n4 = EMB * EMB / 4;       round_kernel<<<(n4 + 255) / 256, 256>>>(Wp,  dWp,  n4);
    }

    dim3 g1(MTOT / 128, 18);
    qkv_kernel<<<g1, 256>>>(bqk, bv);

    dim3 g2(SEQ / 128, BH);
    flash_kernel<<<g2, 128>>>();

    dim3 g4(MTOT / 128, EMB / 128);
    proj_kernel<<<g4, 256>>>(bp, out);
}

// round 13
// speedup vs baseline: 4.0278x; 1.1181x over previous
#include <cuda_runtime.h>
#include <cuda_bf16.h>
#include <cstdint>

// Problem constants
#define BATCH 16
#define SEQ   1024
#define EMB   768
#define NH    12
#define HD    64
#define BH    (BATCH*NH)  // 192
#define MTOT  (BATCH*SEQ) // 16384

// Scratch (allocation-free: __device__ globals)
__device__ float g_Q[(size_t)BH*SEQ*HD];
__device__ float g_K[(size_t)BH*SEQ*HD];
__device__ float g_V[(size_t)BH*SEQ*HD];
__device__ float g_C[(size_t)MTOT*EMB];
// tf32-pre-rounded copies of inputs
__device__ float g_X[(size_t)MTOT*EMB];
__device__ float g_Wqk[(size_t)EMB*2*EMB];
__device__ float g_Wv[(size_t)EMB*EMB];
__device__ float g_Wp[(size_t)EMB*EMB];

// ---------------------------------------------------------------------------
// tf32 + cp.async helpers
// ---------------------------------------------------------------------------
__device__ __forceinline__ uint32_t to_tf32(float f) {
    uint32_t u;
    asm("cvt.rna.tf32.f32 %0, %1;" : "=r"(u) : "f"(f));
    return u;
}

__device__ __forceinline__ void mma8(float* c, const uint32_t* a, const uint32_t* b) {
    asm volatile(
        "mma.sync.aligned.m16n8k8.row.col.f32.tf32.tf32.f32 "
        "{%0,%1,%2,%3},{%4,%5,%6,%7},{%8,%9},{%0,%1,%2,%3};"
        : "+f"(c[0]), "+f"(c[1]), "+f"(c[2]), "+f"(c[3])
        : "r"(a[0]), "r"(a[1]), "r"(a[2]), "r"(a[3]), "r"(b[0]), "r"(b[1]));
}

__device__ __forceinline__ void cp16(uint32_t smem, const void* g) {
    asm volatile("cp.async.cg.shared.global [%0], [%1], 16;\n" :: "r"(smem), "l"(g));
}
__device__ __forceinline__ void cp_commit() {
    asm volatile("cp.async.commit_group;\n");
}
__device__ __forceinline__ void cp_wait2() {
    asm volatile("cp.async.wait_group 2;\n");
}

// SMEM strides
#define LDA8 12      // A tile [128][12] (BK=8): bank g*12+tig all-distinct over 32 lanes
#define LDB8 136     // B tile [8][136], %32==8 -> bank 8*tig+g distinct

// Flash strides
#define LDK 68
#define LDV 72
#define LDP 36

#define NSTG 4

// ---------------------------------------------------------------------------
// Kernel 0: round fp32 -> tf32-representable fp32 (vectorized).
// ---------------------------------------------------------------------------
__global__ void __launch_bounds__(256) round_kernel(
    const float* __restrict__ in, float* __restrict__ out, int n4)
{
    int i = blockIdx.x * 256 + threadIdx.x;
    if (i < n4) {
        float4 v = *(const float4*)&in[(size_t)i * 4];
        uint4 t = { to_tf32(v.x), to_tf32(v.y), to_tf32(v.z), to_tf32(v.w) };
        *(uint4*)&out[(size_t)i * 4] = t;
    }
}

// ---------------------------------------------------------------------------
// Kernel 1: fused QKV projection. cp.async 4-stage, BK=8, ONE sync/iter.
// 128 threads = 4 warps (2x2), warp tile 64x64, block tile 128x128.
// ---------------------------------------------------------------------------
__global__ void __launch_bounds__(128, 2) qkv_kernel(
    const float* __restrict__ bqk, const float* __restrict__ bv)
{
    const int bn  = blockIdx.y;
    const bool isV = (bn >= 12);
    const float* Bmat = isV ? g_Wv : g_Wqk;
    const int ldb     = isV ? 768 : 1536;
    const int n0      = isV ? (bn - 12) * 128 : bn * 128;
    const float* bias = isV ? bv : bqk;
    const int m0 = blockIdx.x * 128;

    __shared__ uint32_t As[NSTG][128 * LDA8];
    __shared__ uint32_t Bs[NSTG][8 * LDB8];

    const int tid = threadIdx.x;
    const int w = tid >> 5, lane = tid & 31;
    const int g = lane >> 2, tig = lane & 3;
    const int wm = (w >> 1) * 64, wn = (w & 1) * 64;

    // cp.async coords: A 128x8 = 256 float4 (2/thread); B 8x128 = 256 float4
    const int ar0 = tid >> 1,         ak0 = (tid & 1) << 2;
    const int ar1 = (128 + tid) >> 1, ak1 = ((128 + tid) & 1) << 2;
    const int br0 = tid >> 5,         bc0 = (tid & 31) << 2;
    const int br1 = (128 + tid) >> 5, bc1 = ((128 + tid) & 31) << 2;

    uint32_t sA[NSTG][2], sB[NSTG][2];
    #pragma unroll
    for (int s = 0; s < NSTG; s++) {
        sA[s][0] = (uint32_t)__cvta_generic_to_shared(&As[s][ar0 * LDA8 + ak0]);
        sA[s][1] = (uint32_t)__cvta_generic_to_shared(&As[s][ar1 * LDA8 + ak1]);
        sB[s][0] = (uint32_t)__cvta_generic_to_shared(&Bs[s][br0 * LDB8 + bc0]);
        sB[s][1] = (uint32_t)__cvta_generic_to_shared(&Bs[s][br1 * LDB8 + bc1]);
    }

    float acc[4][8][4];
    #pragma unroll
    for (int i = 0; i < 4; i++)
        #pragma unroll
        for (int j = 0; j < 8; j++)
            #pragma unroll
            for (int r = 0; r < 4; r++) acc[i][j][r] = 0.f;

    const int NIT = EMB / 8;   // 96

    // Prologue: issue tiles 0..2 into stages 0..2
    #pragma unroll
    for (int t = 0; t < 3; t++) {
        const int kt = t * 8;
        cp16(sA[t][0], &g_X[(size_t)(m0 + ar0) * EMB + kt + ak0]);
        cp16(sA[t][1], &g_X[(size_t)(m0 + ar1) * EMB + kt + ak1]);
        cp16(sB[t][0], &Bmat[(size_t)(kt + br0) * ldb + n0 + bc0]);
        cp16(sB[t][1], &Bmat[(size_t)(kt + br1) * ldb + n0 + bc1]);
        cp_commit();
    }

    for (int it = 0; it < NIT; it++) {
        const int st = it & (NSTG - 1);
        cp_wait2();            // group 'it' (tile it) complete
        __syncthreads();       // visible to all; stage (it-1)%4 free to refill

        // Refill stage (it+3)%4 with tile it+3 (empty commit keeps group math)
        if (it + 3 < NIT) {
            const int kt = (it + 3) * 8;
            const int ns = (it + 3) & (NSTG - 1);
            cp16(sA[ns][0], &g_X[(size_t)(m0 + ar0) * EMB + kt + ak0]);
            cp16(sA[ns][1], &g_X[(size_t)(m0 + ar1) * EMB + kt + ak1]);
            cp16(sB[ns][0], &Bmat[(size_t)(kt + br0) * ldb + n0 + bc0]);
            cp16(sB[ns][1], &Bmat[(size_t)(kt + br1) * ldb + n0 + bc1]);
        }
        cp_commit();

        // MMA on stage st (single k8 step)
        uint32_t a[4][4], b[8][2];
        #pragma unroll
        for (int mi = 0; mi < 4; mi++) {
            int base = (wm + mi * 16 + g) * LDA8 + tig;
            a[mi][0] = As[st][base];
            a[mi][1] = As[st][base + 8 * LDA8];
            a[mi][2] = As[st][base + 4];
            a[mi][3] = As[st][base + 8 * LDA8 + 4];
        }
        #pragma unroll
        for (int ni = 0; ni < 8; ni++) {
            int col = wn + ni * 8 + g;
            b[ni][0] = Bs[st][tig * LDB8 + col];
            b[ni][1] = Bs[st][(tig + 4) * LDB8 + col];
        }
        #pragma unroll
        for (int mi = 0; mi < 4; mi++)
            #pragma unroll
            for (int ni = 0; ni < 8; ni++)
                mma8(acc[mi][ni], a[mi], b[ni]);
    }

    // Epilogue: bias + scatter, stored tf32-rounded (flash reads raw bits)
    #pragma unroll
    for (int mi = 0; mi < 4; mi++) {
        #pragma unroll
        for (int rr = 0; rr < 2; rr++) {
            int gm = m0 + wm + mi * 16 + g + rr * 8;
            int bb = gm >> 10, nn = gm & 1023;
            #pragma unroll
            for (int ni = 0; ni < 8; ni++) {
                #pragma unroll
                for (int cc = 0; cc < 2; cc++) {
                    int c = n0 + wn + ni * 8 + tig * 2 + cc;
                    float val = __uint_as_float(to_tf32(acc[mi][ni][rr * 2 + cc] + bias[c]));
                    if (isV) {
                        int h = c >> 6, dv = c & 63;
                        g_V[(((size_t)(bb * NH + h)) * SEQ + nn) * HD + dv] = val;
                    } else {
                        int h = c >> 7, rem = c & 127;
                        int di = rem >> 1;
                        size_t idx = (((size_t)(bb * NH + h)) * SEQ + nn) * HD + di;
                        if (rem & 1) g_K[idx] = val; else g_Q[idx] = val;
                    }
                }
            }
        }
    }
}

// ---------------------------------------------------------------------------
// Kernel 2: fused flash attention (unchanged from R12 — best known good).
// ---------------------------------------------------------------------------
__global__ void __launch_bounds__(128) flash_kernel()
{
    __shared__ uint32_t Ks[32 * LDK];
    __shared__ uint32_t Vs[32 * LDV];
    __shared__ uint32_t Ps[128 * LDP];

    const int bh = blockIdx.y;
    const int bb = bh / NH, h = bh % NH;
    const int q0 = blockIdx.x * 128;
    const float* Qg = g_Q + (size_t)bh * SEQ * HD;
    const float* Kg = g_K + (size_t)bh * SEQ * HD;
    const float* Vg = g_V + (size_t)bh * SEQ * HD;

    const int tid = threadIdx.x;
    const int w = tid >> 5, lane = tid & 31;
    const int g = lane >> 2, tig = lane & 3;
    const int wm = w * 32;

    uint32_t qa[2][8][4];
    #pragma unroll
    for (int half = 0; half < 2; half++) {
        #pragma unroll
        for (int p = 0; p < 8; p++) {
            int lin = p * 128 + tid;
            int r = lin >> 3, c4 = (lin & 7) << 2;
            float4 v = *(const float4*)&Qg[(size_t)(q0 + r) * HD + half * 32 + c4];
            uint4 t = { __float_as_uint(v.x * 0.125f), __float_as_uint(v.y * 0.125f),
                        __float_as_uint(v.z * 0.125f), __float_as_uint(v.w * 0.125f) };
            *(uint4*)&Ps[r * LDP + c4] = t;
        }
        __syncthreads();
        #pragma unroll
        for (int ksl = 0; ksl < 4; ksl++) {
            #pragma unroll
            for (int mi = 0; mi < 2; mi++) {
                int base = (wm + mi * 16 + g) * LDP + ksl * 8 + tig;
                qa[mi][half * 4 + ksl][0] = Ps[base];
                qa[mi][half * 4 + ksl][1] = Ps[base + 8 * LDP];
                qa[mi][half * 4 + ksl][2] = Ps[base + 4];
                qa[mi][half * 4 + ksl][3] = Ps[base + 8 * LDP + 4];
            }
        }
        __syncthreads();
    }

    float O[2][8][4];
    #pragma unroll
    for (int mi = 0; mi < 2; mi++)
        #pragma unroll
        for (int ni = 0; ni < 8; ni++)
            #pragma unroll
            for (int r = 0; r < 4; r++) O[mi][ni][r] = 0.f;
    float m[4] = { -1e30f, -1e30f, -1e30f, -1e30f };
    float l[4] = { 0.f, 0.f, 0.f, 0.f };

    uint4 rk[4], rv[4];
    #pragma unroll
    for (int p = 0; p < 4; p++) {
        int lin = p * 128 + tid;
        int r = lin >> 4, c4 = (lin & 15) << 2;
        rk[p] = *(const uint4*)&Kg[(size_t)r * HD + c4];
        rv[p] = *(const uint4*)&Vg[(size_t)r * HD + c4];
    }

    for (int kt = 0; kt < SEQ; kt += 32) {
        __syncthreads();
        #pragma unroll
        for (int p = 0; p < 4; p++) {
            int lin = p * 128 + tid;
            int r = lin >> 4, c4 = (lin & 15) << 2;
            *(uint4*)&Ks[r * LDK + c4] = rk[p];
            *(uint4*)&Vs[r * LDV + c4] = rv[p];
        }
        __syncthreads();

        float s[2][4][4];
        #pragma unroll
        for (int mi = 0; mi < 2; mi++)
            #pragma unroll
            for (int ni = 0; ni < 4; ni++)
                #pragma unroll
                for (int r = 0; r < 4; r++) s[mi][ni][r] = 0.f;

        #pragma unroll
        for (int ks = 0; ks < 8; ks++) {
            uint32_t b[4][2];
            #pragma unroll
            for (int ni = 0; ni < 4; ni++) {
                int base = (ni * 8 + g) * LDK + ks * 8 + tig;
                b[ni][0] = Ks[base];
                b[ni][1] = Ks[base + 4];
            }
            #pragma unroll
            for (int mi = 0; mi < 2; mi++)
                #pragma unroll
                for (int ni = 0; ni < 4; ni++)
                    mma8(s[mi][ni], qa[mi][ks], b[ni]);
        }

        if (kt + 32 < SEQ) {
            #pragma unroll
            for (int p = 0; p < 4; p++) {
                int lin = p * 128 + tid;
                int r = lin >> 4, c4 = (lin & 15) << 2;
                rk[p] = *(const uint4*)&Kg[(size_t)(kt + 32 + r) * HD + c4];
                rv[p] = *(const uint4*)&Vg[(size_t)(kt + 32 + r) * HD + c4];
            }
        }

        float scl[4];
        #pragma unroll
        for (int mi = 0; mi < 2; mi++) {
            #pragma unroll
            for (int rr = 0; rr < 2; rr++) {
                int si = mi * 2 + rr;
                float rmax = -1e30f;
                #pragma unroll
                for (int ni = 0; ni < 4; ni++) {
                    rmax = fmaxf(rmax, s[mi][ni][rr * 2]);
                    rmax = fmaxf(rmax, s[mi][ni][rr * 2 + 1]);
                }
                rmax = fmaxf(rmax, __shfl_xor_sync(~0u, rmax, 1));
                rmax = fmaxf(rmax, __shfl_xor_sync(~0u, rmax, 2));
                float mnew = fmaxf(m[si], rmax);
                float sc = __expf(m[si] - mnew);
                float rs = 0.f;
                #pragma unroll
                for (int ni = 0; ni < 4; ni++) {
                    float p0 = __expf(s[mi][ni][rr * 2]     - mnew);
                    float p1 = __expf(s[mi][ni][rr * 2 + 1] - mnew);
                    s[mi][ni][rr * 2]     = p0;
                    s[mi][ni][rr * 2 + 1] = p1;
                    rs += p0 + p1;
                }
                rs += __shfl_xor_sync(~0u, rs, 1);
                rs += __shfl_xor_sync(~0u, rs, 2);
                l[si] = l[si] * sc + rs;
                m[si] = mnew;
                scl[si] = sc;
            }
        }

        #pragma unroll
        for (int mi = 0; mi < 2; mi++)
            #pragma unroll
            for (int ni = 0; ni < 8; ni++)
                #pragma unroll
                for (int rr = 0; rr < 2; rr++) {
                    O[mi][ni][rr * 2]     *= scl[mi * 2 + rr];
                    O[mi][ni][rr * 2 + 1] *= scl[mi * 2 + rr];
                }

        #pragma unroll
        for (int mi = 0; mi < 2; mi++)
            #pragma unroll
            for (int rr = 0; rr < 2; rr++) {
                int row = wm + mi * 16 + rr * 8 + g;
                #pragma unroll
                for (int ni = 0; ni < 4; ni++) {
                    uint2 t = { to_tf32(s[mi][ni][rr * 2]),
                                to_tf32(s[mi][ni][rr * 2 + 1]) };
                    *(uint2*)&Ps[row * LDP + ni * 8 + tig * 2] = t;
                }
            }
        __syncwarp();

        #pragma unroll
        for (int ks = 0; ks < 4; ks++) {
            uint32_t a[2][4], b[8][2];
            #pragma unroll
            for (int mi = 0; mi < 2; mi++) {
                int base = (wm + mi * 16 + g) * LDP + ks * 8 + tig;
                a[mi][0] = Ps[base];
                a[mi][1] = Ps[base + 8 * LDP];
                a[mi][2] = Ps[base + 4];
                a[mi][3] = Ps[base + 8 * LDP + 4];
            }
            #pragma unroll
            for (int ni = 0; ni < 8; ni++) {
                b[ni][0] = Vs[(ks * 8 + tig) * LDV + ni * 8 + g];
                b[ni][1] = Vs[(ks * 8 + tig + 4) * LDV + ni * 8 + g];
            }
            #pragma unroll
            for (int mi = 0; mi < 2; mi++)
                #pragma unroll
                for (int ni = 0; ni < 8; ni++)
                    mma8(O[mi][ni], a[mi], b[ni]);
        }
        __syncwarp();
    }

    #pragma unroll
    for (int mi = 0; mi < 2; mi++)
        #pragma unroll
        for (int rr = 0; rr < 2; rr++) {
            float inv = 1.0f / l[mi * 2 + rr];
            int nn = q0 + wm + mi * 16 + rr * 8 + g;
            #pragma unroll
            for (int ni = 0; ni < 8; ni++) {
                int col = ni * 8 + tig * 2;
                uint2 v = { to_tf32(O[mi][ni][rr * 2] * inv),
                            to_tf32(O[mi][ni][rr * 2 + 1] * inv) };
                *(uint2*)&g_C[((size_t)(bb * SEQ + nn)) * EMB + h * HD + col] = v;
            }
        }
}

// ---------------------------------------------------------------------------
// Kernel 3: out = ctx @ W_proj + b_proj. cp.async 4-stage, BK=8, 1 sync/iter.
// 128 threads, warp tile 64x64.
// ---------------------------------------------------------------------------
__global__ void __launch_bounds__(128, 2) proj_kernel(
    const float* __restrict__ bp, float* __restrict__ out)
{
    __shared__ uint32_t As[NSTG][128 * LDA8];
    __shared__ uint32_t Bs[NSTG][8 * LDB8];

    const int tid = threadIdx.x;
    const int w = tid >> 5, lane = tid & 31;
    const int g = lane >> 2, tig = lane & 3;
    const int wm = (w >> 1) * 64, wn = (w & 1) * 64;
    const int m0 = blockIdx.x * 128, n0 = blockIdx.y * 128;

    const int ar0 = tid >> 1,         ak0 = (tid & 1) << 2;
    const int ar1 = (128 + tid) >> 1, ak1 = ((128 + tid) & 1) << 2;
    const int br0 = tid >> 5,         bc0 = (tid & 31) << 2;
    const int br1 = (128 + tid) >> 5, bc1 = ((128 + tid) & 31) << 2;

    uint32_t sA[NSTG][2], sB[NSTG][2];
    #pragma unroll
    for (int s = 0; s < NSTG; s++) {
        sA[s][0] = (uint32_t)__cvta_generic_to_shared(&As[s][ar0 * LDA8 + ak0]);
        sA[s][1] = (uint32_t)__cvta_generic_to_shared(&As[s][ar1 * LDA8 + ak1]);
        sB[s][0] = (uint32_t)__cvta_generic_to_shared(&Bs[s][br0 * LDB8 + bc0]);
        sB[s][1] = (uint32_t)__cvta_generic_to_shared(&Bs[s][br1 * LDB8 + bc1]);
    }

    float acc[4][8][4];
    #pragma unroll
    for (int i = 0; i < 4; i++)
        #pragma unroll
        for (int j = 0; j < 8; j++)
            #pragma unroll
            for (int r = 0; r < 4; r++) acc[i][j][r] = 0.f;

    const int NIT = EMB / 8;

    #pragma unroll
    for (int t = 0; t < 3; t++) {
        const int kt = t * 8;
        cp16(sA[t][0], &g_C[(size_t)(m0 + ar0) * EMB + kt + ak0]);
        cp16(sA[t][1], &g_C[(size_t)(m0 + ar1) * EMB + kt + ak1]);
        cp16(sB[t][0], &g_Wp[(size_t)(kt + br0) * EMB + n0 + bc0]);
        cp16(sB[t][1], &g_Wp[(size_t)(kt + br1) * EMB + n0 + bc1]);
        cp_commit();
    }

    for (int it = 0; it < NIT; it++) {
        const int st = it & (NSTG - 1);
        cp_wait2();
        __syncthreads();

        if (it + 3 < NIT) {
            const int kt = (it + 3) * 8;
            const int ns = (it + 3) & (NSTG - 1);
            cp16(sA[ns][0], &g_C[(size_t)(m0 + ar0) * EMB + kt + ak0]);
            cp16(sA[ns][1], &g_C[(size_t)(m0 + ar1) * EMB + kt + ak1]);
            cp16(sB[ns][0], &g_Wp[(size_t)(kt + br0) * EMB + n0 + bc0]);
            cp16(sB[ns][1], &g_Wp[(size_t)(kt + br1) * EMB + n0 + bc1]);
        }
        cp_commit();

        uint32_t a[4][4], b[8][2];
        #pragma unroll
        for (int mi = 0; mi < 4; mi++) {
            int base = (wm + mi * 16 + g) * LDA8 + tig;
            a[mi][0] = As[st][base];
            a[mi][1] = As[st][base + 8 * LDA8];
            a[mi][2] = As[st][base + 4];
            a[mi][3] = As[st][base + 8 * LDA8 + 4];
        }
        #pragma unroll
        for (int ni = 0; ni < 8; ni++) {
            int col = wn + ni * 8 + g;
            b[ni][0] = Bs[st][tig * LDB8 + col];
            b[ni][1] = Bs[st][(tig + 4) * LDB8 + col];
        }
        #pragma unroll
        for (int mi = 0; mi < 4; mi++)
            #pragma unroll
            for (int ni = 0; ni < 8; ni++)
                mma8(acc[mi][ni], a[mi], b[ni]);
    }

    #pragma unroll
    for (int mi = 0; mi < 4; mi++)
        #pragma unroll
        for (int rr = 0; rr < 2; rr++) {
            int gm = m0 + wm + mi * 16 + g + rr * 8;
            #pragma unroll
            for (int ni = 0; ni < 8; ni++) {
                int c = n0 + wn + ni * 8 + tig * 2;
                float2 v = { acc[mi][ni][rr * 2] + bp[c],
                             acc[mi][ni][rr * 2 + 1] + bp[c + 1] };
                *(float2*)&out[(size_t)gm * EMB + c] = v;
            }
        }
}

// ---------------------------------------------------------------------------
extern "C" void kernel_launch(void* const* d_in, const int* in_sizes, int n_in,
                              void* d_out, int out_size)
{
    const float* x   = (const float*)d_in[0];
    const float* Wqk = (const float*)d_in[1];
    const float* bqk = (const float*)d_in[2];
    const float* Wv  = (const float*)d_in[3];
    const float* bv  = (const float*)d_in[4];
    const float* Wp  = (const float*)d_in[5];
    const float* bp  = (const float*)d_in[6];
    float* out = (float*)d_out;

    float *dX, *dWqk, *dWv, *dWp;
    cudaGetSymbolAddress((void**)&dX,   g_X);
    cudaGetSymbolAddress((void**)&dWqk, g_Wqk);
    cudaGetSymbolAddress((void**)&dWv,  g_Wv);
    cudaGetSymbolAddress((void**)&dWp,  g_Wp);

    {
        int n4;
        n4 = MTOT * EMB / 4;      round_kernel<<<(n4 + 255) / 256, 256>>>(x,   dX,   n4);
        n4 = EMB * 2 * EMB / 4;   round_kernel<<<(n4 + 255) / 256, 256>>>(Wqk, dWqk, n4);
        n4 = EMB * EMB / 4;       round_kernel<<<(n4 + 255) / 256, 256>>>(Wv,  dWv,  n4);
        n4 = EMB * EMB / 4;       round_kernel<<<(n4 + 255) / 256, 256>>>(Wp,  dWp,  n4);
    }

    dim3 g1(MTOT / 128, 18);
    qkv_kernel<<<g1, 128>>>(bqk, bv);

    dim3 g2(SEQ / 128, BH);
    flash_kernel<<<g2, 128>>>();

    dim3 g4(MTOT / 128, EMB / 128);
    proj_kernel<<<g4, 128>>>(bp, out);
}

// round 14
// speedup vs baseline: 4.0750x; 1.0117x over previous
#include <cuda_runtime.h>
#include <cuda_bf16.h>
#include <cstdint>

// Problem constants
#define BATCH 16
#define SEQ   1024
#define EMB   768
#define NH    12
#define HD    64
#define BH    (BATCH*NH)  // 192
#define MTOT  (BATCH*SEQ) // 16384

// Scratch (allocation-free: __device__ globals)
__device__ float g_Q[(size_t)BH*SEQ*HD];
__device__ float g_K[(size_t)BH*SEQ*HD];
__device__ float g_V[(size_t)BH*SEQ*HD];
__device__ float g_C[(size_t)MTOT*EMB];
// tf32-pre-rounded copies of inputs
__device__ float g_X[(size_t)MTOT*EMB];
__device__ float g_Wqk[(size_t)EMB*2*EMB];
__device__ float g_Wv[(size_t)EMB*EMB];
__device__ float g_Wp[(size_t)EMB*EMB];

// ---------------------------------------------------------------------------
// tf32 + cp.async helpers
// ---------------------------------------------------------------------------
__device__ __forceinline__ uint32_t to_tf32(float f) {
    uint32_t u;
    asm("cvt.rna.tf32.f32 %0, %1;" : "=r"(u) : "f"(f));
    return u;
}

__device__ __forceinline__ float ex2(float x) {
    float y;
    asm("ex2.approx.ftz.f32 %0, %1;" : "=f"(y) : "f"(x));
    return y;
}

__device__ __forceinline__ void mma8(float* c, const uint32_t* a, const uint32_t* b) {
    asm volatile(
        "mma.sync.aligned.m16n8k8.row.col.f32.tf32.tf32.f32 "
        "{%0,%1,%2,%3},{%4,%5,%6,%7},{%8,%9},{%0,%1,%2,%3};"
        : "+f"(c[0]), "+f"(c[1]), "+f"(c[2]), "+f"(c[3])
        : "r"(a[0]), "r"(a[1]), "r"(a[2]), "r"(a[3]), "r"(b[0]), "r"(b[1]));
}

__device__ __forceinline__ void cp16(uint32_t smem, const void* g) {
    asm volatile("cp.async.cg.shared.global [%0], [%1], 16;\n" :: "r"(smem), "l"(g));
}
__device__ __forceinline__ void cp_commit() {
    asm volatile("cp.async.commit_group;\n");
}
__device__ __forceinline__ void cp_wait2() {
    asm volatile("cp.async.wait_group 2;\n");
}

// SMEM strides
#define LDA8 12      // GEMM A tile [128][12] (BK=8)
#define LDB8 136     // GEMM B tile [8][136]

// Flash strides
#define LDK 68       // K tile [32][68], %32==4
#define LDV 72       // V tile [32][72], %32==8
#define LDP 36       // Q staging [128][36], %32==4

#define NSTG 4

// Q scale: 1/sqrt(64) * log2(e), folded so softmax runs in base-2 domain
#define QSCALE 0.18033688011112042f

// ---------------------------------------------------------------------------
// Kernel 0: round fp32 -> tf32-representable fp32 (vectorized).
// ---------------------------------------------------------------------------
__global__ void __launch_bounds__(256) round_kernel(
    const float* __restrict__ in, float* __restrict__ out, int n4)
{
    int i = blockIdx.x * 256 + threadIdx.x;
    if (i < n4) {
        float4 v = *(const float4*)&in[(size_t)i * 4];
        uint4 t = { to_tf32(v.x), to_tf32(v.y), to_tf32(v.z), to_tf32(v.w) };
        *(uint4*)&out[(size_t)i * 4] = t;
    }
}

// ---------------------------------------------------------------------------
// Kernel 1: fused QKV projection. cp.async 4-stage, BK=8 (unchanged R13).
// ---------------------------------------------------------------------------
__global__ void __launch_bounds__(128, 2) qkv_kernel(
    const float* __restrict__ bqk, const float* __restrict__ bv)
{
    const int bn  = blockIdx.y;
    const bool isV = (bn >= 12);
    const float* Bmat = isV ? g_Wv : g_Wqk;
    const int ldb     = isV ? 768 : 1536;
    const int n0      = isV ? (bn - 12) * 128 : bn * 128;
    const float* bias = isV ? bv : bqk;
    const int m0 = blockIdx.x * 128;

    __shared__ uint32_t As[NSTG][128 * LDA8];
    __shared__ uint32_t Bs[NSTG][8 * LDB8];

    const int tid = threadIdx.x;
    const int w = tid >> 5, lane = tid & 31;
    const int g = lane >> 2, tig = lane & 3;
    const int wm = (w >> 1) * 64, wn = (w & 1) * 64;

    const int ar0 = tid >> 1,         ak0 = (tid & 1) << 2;
    const int ar1 = (128 + tid) >> 1, ak1 = ((128 + tid) & 1) << 2;
    const int br0 = tid >> 5,         bc0 = (tid & 31) << 2;
    const int br1 = (128 + tid) >> 5, bc1 = ((128 + tid) & 31) << 2;

    uint32_t sA[NSTG][2], sB[NSTG][2];
    #pragma unroll
    for (int s = 0; s < NSTG; s++) {
        sA[s][0] = (uint32_t)__cvta_generic_to_shared(&As[s][ar0 * LDA8 + ak0]);
        sA[s][1] = (uint32_t)__cvta_generic_to_shared(&As[s][ar1 * LDA8 + ak1]);
        sB[s][0] = (uint32_t)__cvta_generic_to_shared(&Bs[s][br0 * LDB8 + bc0]);
        sB[s][1] = (uint32_t)__cvta_generic_to_shared(&Bs[s][br1 * LDB8 + bc1]);
    }

    float acc[4][8][4];
    #pragma unroll
    for (int i = 0; i < 4; i++)
        #pragma unroll
        for (int j = 0; j < 8; j++)
            #pragma unroll
            for (int r = 0; r < 4; r++) acc[i][j][r] = 0.f;

    const int NIT = EMB / 8;

    #pragma unroll
    for (int t = 0; t < 3; t++) {
        const int kt = t * 8;
        cp16(sA[t][0], &g_X[(size_t)(m0 + ar0) * EMB + kt + ak0]);
        cp16(sA[t][1], &g_X[(size_t)(m0 + ar1) * EMB + kt + ak1]);
        cp16(sB[t][0], &Bmat[(size_t)(kt + br0) * ldb + n0 + bc0]);
        cp16(sB[t][1], &Bmat[(size_t)(kt + br1) * ldb + n0 + bc1]);
        cp_commit();
    }

    for (int it = 0; it < NIT; it++) {
        const int st = it & (NSTG - 1);
        cp_wait2();
        __syncthreads();

        if (it + 3 < NIT) {
            const int kt = (it + 3) * 8;
            const int ns = (it + 3) & (NSTG - 1);
            cp16(sA[ns][0], &g_X[(size_t)(m0 + ar0) * EMB + kt + ak0]);
            cp16(sA[ns][1], &g_X[(size_t)(m0 + ar1) * EMB + kt + ak1]);
            cp16(sB[ns][0], &Bmat[(size_t)(kt + br0) * ldb + n0 + bc0]);
            cp16(sB[ns][1], &Bmat[(size_t)(kt + br1) * ldb + n0 + bc1]);
        }
        cp_commit();

        uint32_t a[4][4], b[8][2];
        #pragma unroll
        for (int mi = 0; mi < 4; mi++) {
            int base = (wm + mi * 16 + g) * LDA8 + tig;
            a[mi][0] = As[st][base];
            a[mi][1] = As[st][base + 8 * LDA8];
            a[mi][2] = As[st][base + 4];
            a[mi][3] = As[st][base + 8 * LDA8 + 4];
        }
        #pragma unroll
        for (int ni = 0; ni < 8; ni++) {
            int col = wn + ni * 8 + g;
            b[ni][0] = Bs[st][tig * LDB8 + col];
            b[ni][1] = Bs[st][(tig + 4) * LDB8 + col];
        }
        #pragma unroll
        for (int mi = 0; mi < 4; mi++)
            #pragma unroll
            for (int ni = 0; ni < 8; ni++)
                mma8(acc[mi][ni], a[mi], b[ni]);
    }

    #pragma unroll
    for (int mi = 0; mi < 4; mi++) {
        #pragma unroll
        for (int rr = 0; rr < 2; rr++) {
            int gm = m0 + wm + mi * 16 + g + rr * 8;
            int bb = gm >> 10, nn = gm & 1023;
            #pragma unroll
            for (int ni = 0; ni < 8; ni++) {
                #pragma unroll
                for (int cc = 0; cc < 2; cc++) {
                    int c = n0 + wn + ni * 8 + tig * 2 + cc;
                    float val = __uint_as_float(to_tf32(acc[mi][ni][rr * 2 + cc] + bias[c]));
                    if (isV) {
                        int h = c >> 6, dv = c & 63;
                        g_V[(((size_t)(bb * NH + h)) * SEQ + nn) * HD + dv] = val;
                    } else {
                        int h = c >> 7, rem = c & 127;
                        int di = rem >> 1;
                        size_t idx = (((size_t)(bb * NH + h)) * SEQ + nn) * HD + di;
                        if (rem & 1) g_K[idx] = val; else g_Q[idx] = val;
                    }
                }
            }
        }
    }
}

// ---------------------------------------------------------------------------
// Kernel 2: flash attention V2.
//  - O^T = V^T @ P^T: P never touches SMEM (B-frags built by warp shuffles
//    from the S C-fragments).
//  - K/V double-buffered in SMEM (2 stages), ONE __syncthreads per kv tile,
//    global prefetch one full iteration ahead.
//  - base-2 softmax (0.125*log2e folded into Q).
// SMEM: 2*(32*68) + 2*(32*72) = 8960 u32 = 35 KB (Q staging reuses front).
// ---------------------------------------------------------------------------
#define KS_OFF(s) ((s) * (32 * LDK))
#define VS_OFF(s) (2 * 32 * LDK + (s) * (32 * LDV))

__global__ void __launch_bounds__(128) flash_kernel()
{
    __shared__ uint32_t buf[2 * 32 * LDK + 2 * 32 * LDV];   // 8960 u32

    const int bh = blockIdx.y;
    const int bb = bh / NH, h = bh % NH;
    const int q0 = blockIdx.x * 128;
    const float* Qg = g_Q + (size_t)bh * SEQ * HD;
    const float* Kg = g_K + (size_t)bh * SEQ * HD;
    const float* Vg = g_V + (size_t)bh * SEQ * HD;

    const int tid = threadIdx.x;
    const int w = tid >> 5, lane = tid & 31;
    const int g = lane >> 2, tig = lane & 3;
    const int wm = w * 32;

    // --- Prologue 1: Q fragments into registers (scaled, tf32), staged
    // through buf[0 .. 128*36) which is later reused for K/V stages. ---
    uint32_t qa[2][8][4];
    #pragma unroll
    for (int half = 0; half < 2; half++) {
        #pragma unroll
        for (int p = 0; p < 8; p++) {
            int lin = p * 128 + tid;
            int r = lin >> 3, c4 = (lin & 7) << 2;
            float4 v = *(const float4*)&Qg[(size_t)(q0 + r) * HD + half * 32 + c4];
            uint4 t = { to_tf32(v.x * QSCALE), to_tf32(v.y * QSCALE),
                        to_tf32(v.z * QSCALE), to_tf32(v.w * QSCALE) };
            *(uint4*)&buf[r * LDP + c4] = t;
        }
        __syncthreads();
        #pragma unroll
        for (int ksl = 0; ksl < 4; ksl++) {
            #pragma unroll
            for (int mi = 0; mi < 2; mi++) {
                int base = (wm + mi * 16 + g) * LDP + ksl * 8 + tig;
                qa[mi][half * 4 + ksl][0] = buf[base];
                qa[mi][half * 4 + ksl][1] = buf[base + 8 * LDP];
                qa[mi][half * 4 + ksl][2] = buf[base + 4];
                qa[mi][half * 4 + ksl][3] = buf[base + 8 * LDP + 4];
            }
        }
        __syncthreads();
    }

    // --- Prologue 2: tile 0 -> stage 0, tile 1 -> regs. ---
    const int lr = tid >> 4;               // row slot base (0..7), +8 per p
    const int lc4 = (tid & 15) << 2;       // col 0..60
    uint4 rk[4], rv[4];
    #pragma unroll
    for (int p = 0; p < 4; p++) {
        int r = lr + p * 8;
        rk[p] = *(const uint4*)&Kg[(size_t)r * HD + lc4];
        rv[p] = *(const uint4*)&Vg[(size_t)r * HD + lc4];
    }
    #pragma unroll
    for (int p = 0; p < 4; p++) {
        int r = lr + p * 8;
        *(uint4*)&buf[KS_OFF(0) + r * LDK + lc4] = rk[p];
        *(uint4*)&buf[VS_OFF(0) + r * LDV + lc4] = rv[p];
    }
    #pragma unroll
    for (int p = 0; p < 4; p++) {
        int r = lr + p * 8;
        rk[p] = *(const uint4*)&Kg[(size_t)(32 + r) * HD + lc4];
        rv[p] = *(const uint4*)&Vg[(size_t)(32 + r) * HD + lc4];
    }
    __syncthreads();

    // O^T accumulator: C-frags (m=dv 64 -> 4 tiles, n=q 32 -> 4 tiles)
    float Ot[4][4][4];
    #pragma unroll
    for (int i = 0; i < 4; i++)
        #pragma unroll
        for (int j = 0; j < 4; j++)
            #pragma unroll
            for (int r = 0; r < 4; r++) Ot[i][j][r] = 0.f;
    float m[4] = { -1e30f, -1e30f, -1e30f, -1e30f };
    float l[4] = { 0.f, 0.f, 0.f, 0.f };

    const int NT = SEQ / 32;   // 32 kv tiles
    for (int it = 0; it < NT; it++) {
        const uint32_t* Kst = buf + KS_OFF(it & 1);
        const uint32_t* Vst = buf + VS_OFF(it & 1);

        // STS tile it+1 (regs->stage s^1; that stage was last read at it-1,
        // protected by the end-of-iteration barrier).
        if (it + 1 < NT) {
            uint32_t* Kw = buf + KS_OFF((it + 1) & 1);
            uint32_t* Vw = buf + VS_OFF((it + 1) & 1);
            #pragma unroll
            for (int p = 0; p < 4; p++) {
                int r = lr + p * 8;
                *(uint4*)&Kw[r * LDK + lc4] = rk[p];
                *(uint4*)&Vw[r * LDV + lc4] = rv[p];
            }
        }
        // LDG tile it+2 -> regs (a full iteration of latency cover)
        if (it + 2 < NT) {
            #pragma unroll
            for (int p = 0; p < 4; p++) {
                int r = (it + 2) * 32 + lr + p * 8;
                rk[p] = *(const uint4*)&Kg[(size_t)r * HD + lc4];
                rv[p] = *(const uint4*)&Vg[(size_t)r * HD + lc4];
            }
        }

        // S = Q@K^T (32q x 32kv per warp), k=64
        float s[2][4][4];
        #pragma unroll
        for (int mi = 0; mi < 2; mi++)
            #pragma unroll
            for (int ni = 0; ni < 4; ni++)
                #pragma unroll
                for (int r = 0; r < 4; r++) s[mi][ni][r] = 0.f;

        #pragma unroll
        for (int ks = 0; ks < 8; ks++) {
            uint32_t b[4][2];
            #pragma unroll
            for (int ni = 0; ni < 4; ni++) {
                int base = (ni * 8 + g) * LDK + ks * 8 + tig;
                b[ni][0] = Kst[base];
                b[ni][1] = Kst[base + 4];
            }
            #pragma unroll
            for (int mi = 0; mi < 2; mi++)
                #pragma unroll
                for (int ni = 0; ni < 4; ni++)
                    mma8(s[mi][ni], qa[mi][ks], b[ni]);
        }

        // Online softmax, base-2 domain (rows in-warp; reduce over tig lanes)
        float scl[4];
        #pragma unroll
        for (int mi = 0; mi < 2; mi++) {
            #pragma unroll
            for (int rr = 0; rr < 2; rr++) {
                int si = mi * 2 + rr;
                float rmax = -1e30f;
                #pragma unroll
                for (int ni = 0; ni < 4; ni++) {
                    rmax = fmaxf(rmax, s[mi][ni][rr * 2]);
                    rmax = fmaxf(rmax, s[mi][ni][rr * 2 + 1]);
                }
                rmax = fmaxf(rmax, __shfl_xor_sync(~0u, rmax, 1));
                rmax = fmaxf(rmax, __shfl_xor_sync(~0u, rmax, 2));
                float mnew = fmaxf(m[si], rmax);
                float sc = ex2(m[si] - mnew);
                float rs = 0.f;
                #pragma unroll
                for (int ni = 0; ni < 4; ni++) {
                    float p0 = ex2(s[mi][ni][rr * 2]     - mnew);
                    float p1 = ex2(s[mi][ni][rr * 2 + 1] - mnew);
                    s[mi][ni][rr * 2]     = p0;
                    s[mi][ni][rr * 2 + 1] = p1;
                    rs += p0 + p1;
                }
                rs += __shfl_xor_sync(~0u, rs, 1);
                rs += __shfl_xor_sync(~0u, rs, 2);
                l[si] = l[si] * sc + rs;
                m[si] = mnew;
                scl[si] = sc;
            }
        }

        // Round P to tf32 in place (operand of the PV mma)
        #pragma unroll
        for (int mi = 0; mi < 2; mi++)
            #pragma unroll
            for (int ni = 0; ni < 4; ni++)
                #pragma unroll
                for (int r = 0; r < 4; r++)
                    s[mi][ni][r] = __uint_as_float(to_tf32(s[mi][ni][r]));

        // Rescale O^T: factor depends on q = 8*n0 + 2*tig + c
        {
            float sce[4], sco[4];
            #pragma unroll
            for (int n0 = 0; n0 < 4; n0++) {
                sce[n0] = __shfl_sync(~0u, scl[n0], tig * 8);
                sco[n0] = __shfl_sync(~0u, scl[n0], tig * 8 + 4);
            }
            #pragma unroll
            for (int mi2 = 0; mi2 < 4; mi2++)
                #pragma unroll
                for (int n0 = 0; n0 < 4; n0++) {
                    Ot[mi2][n0][0] *= sce[n0];
                    Ot[mi2][n0][1] *= sco[n0];
                    Ot[mi2][n0][2] *= sce[n0];
                    Ot[mi2][n0][3] *= sco[n0];
                }
        }

        // O^T += V^T @ P^T  (m=dv64, n=q32, k=kv32)
        const int src0 = g * 4 + (tig >> 1);
        const int src1 = src0 + 2;
        #pragma unroll
        for (int k0 = 0; k0 < 4; k0++) {
            uint32_t a4[4][4];
            #pragma unroll
            for (int mi2 = 0; mi2 < 4; mi2++) {
                int r0 = (k0 * 8 + tig) * LDV + mi2 * 16 + g;
                int r1 = (k0 * 8 + tig + 4) * LDV + mi2 * 16 + g;
                a4[mi2][0] = Vst[r0];
                a4[mi2][1] = Vst[r0 + 8];
                a4[mi2][2] = Vst[r1];
                a4[mi2][3] = Vst[r1 + 8];
            }
            uint32_t bb2[4][2];
            #pragma unroll
            for (int n0 = 0; n0 < 4; n0++) {
                int mi = n0 >> 1, pn = (n0 & 1) * 2;
                float lo0 = __shfl_sync(~0u, s[mi][k0][pn],     src0);
                float hi0 = __shfl_sync(~0u, s[mi][k0][pn + 1], src0);
                float lo1 = __shfl_sync(~0u, s[mi][k0][pn],     src1);
                float hi1 = __shfl_sync(~0u, s[mi][k0][pn + 1], src1);
                bb2[n0][0] = __float_as_uint((tig & 1) ? hi0 : lo0);
                bb2[n0][1] = __float_as_uint((tig & 1) ? hi1 : lo1);
            }
            #pragma unroll
            for (int mi2 = 0; mi2 < 4; mi2++)
                #pragma unroll
                for (int n0 = 0; n0 < 4; n0++)
                    mma8(Ot[mi2][n0], a4[mi2], bb2[n0]);
        }

        __syncthreads();   // all reads of this stage done before it's refilled
    }

    // Epilogue: O = (O^T)^T / l, tf32-rounded for proj's raw-bit reads.
    {
        float linv[4];
        #pragma unroll
        for (int si = 0; si < 4; si++) linv[si] = 1.0f / l[si];
        float ie[4], io[4];
        #pragma unroll
        for (int n0 = 0; n0 < 4; n0++) {
            ie[n0] = __shfl_sync(~0u, linv[n0], tig * 8);
            io[n0] = __shfl_sync(~0u, linv[n0], tig * 8 + 4);
        }
        #pragma unroll
        for (int mi2 = 0; mi2 < 4; mi2++) {
            int dv = mi2 * 16 + g;
            #pragma unroll
            for (int n0 = 0; n0 < 4; n0++) {
                int qg = q0 + wm + n0 * 8 + tig * 2;
                size_t base = ((size_t)(bb * SEQ + qg)) * EMB + h * HD + dv;
                g_C[base]           = __uint_as_float(to_tf32(Ot[mi2][n0][0] * ie[n0]));
                g_C[base + EMB]     = __uint_as_float(to_tf32(Ot[mi2][n0][1] * io[n0]));
                g_C[base + 8]       = __uint_as_float(to_tf32(Ot[mi2][n0][2] * ie[n0]));
                g_C[base + EMB + 8] = __uint_as_float(to_tf32(Ot[mi2][n0][3] * io[n0]));
            }
        }
    }
}

// ---------------------------------------------------------------------------
// Kernel 3: out = ctx @ W_proj + b_proj. cp.async 4-stage, BK=8 (unchanged).
// ---------------------------------------------------------------------------
__global__ void __launch_bounds__(128, 2) proj_kernel(
    const float* __restrict__ bp, float* __restrict__ out)
{
    __shared__ uint32_t As[NSTG][128 * LDA8];
    __shared__ uint32_t Bs[NSTG][8 * LDB8];

    const int tid = threadIdx.x;
    const int w = tid >> 5, lane = tid & 31;
    const int g = lane >> 2, tig = lane & 3;
    const int wm = (w >> 1) * 64, wn = (w & 1) * 64;
    const int m0 = blockIdx.x * 128, n0 = blockIdx.y * 128;

    const int ar0 = tid >> 1,         ak0 = (tid & 1) << 2;
    const int ar1 = (128 + tid) >> 1, ak1 = ((128 + tid) & 1) << 2;
    const int br0 = tid >> 5,         bc0 = (tid & 31) << 2;
    const int br1 = (128 + tid) >> 5, bc1 = ((128 + tid) & 31) << 2;

    uint32_t sA[NSTG][2], sB[NSTG][2];
    #pragma unroll
    for (int s = 0; s < NSTG; s++) {
        sA[s][0] = (uint32_t)__cvta_generic_to_shared(&As[s][ar0 * LDA8 + ak0]);
        sA[s][1] = (uint32_t)__cvta_generic_to_shared(&As[s][ar1 * LDA8 + ak1]);
        sB[s][0] = (uint32_t)__cvta_generic_to_shared(&Bs[s][br0 * LDB8 + bc0]);
        sB[s][1] = (uint32_t)__cvta_generic_to_shared(&Bs[s][br1 * LDB8 + bc1]);
    }

    float acc[4][8][4];
    #pragma unroll
    for (int i = 0; i < 4; i++)
        #pragma unroll
        for (int j = 0; j < 8; j++)
            #pragma unroll
            for (int r = 0; r < 4; r++) acc[i][j][r] = 0.f;

    const int NIT = EMB / 8;

    #pragma unroll
    for (int t = 0; t < 3; t++) {
        const int kt = t * 8;
        cp16(sA[t][0], &g_C[(size_t)(m0 + ar0) * EMB + kt + ak0]);
        cp16(sA[t][1], &g_C[(size_t)(m0 + ar1) * EMB + kt + ak1]);
        cp16(sB[t][0], &g_Wp[(size_t)(kt + br0) * EMB + n0 + bc0]);
        cp16(sB[t][1], &g_Wp[(size_t)(kt + br1) * EMB + n0 + bc1]);
        cp_commit();
    }

    for (int it = 0; it < NIT; it++) {
        const int st = it & (NSTG - 1);
        cp_wait2();
        __syncthreads();

        if (it + 3 < NIT) {
            const int kt = (it + 3) * 8;
            const int ns = (it + 3) & (NSTG - 1);
            cp16(sA[ns][0], &g_C[(size_t)(m0 + ar0) * EMB + kt + ak0]);
            cp16(sA[ns][1], &g_C[(size_t)(m0 + ar1) * EMB + kt + ak1]);
            cp16(sB[ns][0], &g_Wp[(size_t)(kt + br0) * EMB + n0 + bc0]);
            cp16(sB[ns][1], &g_Wp[(size_t)(kt + br1) * EMB + n0 + bc1]);
        }
        cp_commit();

        uint32_t a[4][4], b[8][2];
        #pragma unroll
        for (int mi = 0; mi < 4; mi++) {
            int base = (wm + mi * 16 + g) * LDA8 + tig;
            a[mi][0] = As[st][base];
            a[mi][1] = As[st][base + 8 * LDA8];
            a[mi][2] = As[st][base + 4];
            a[mi][3] = As[st][base + 8 * LDA8 + 4];
        }
        #pragma unroll
        for (int ni = 0; ni < 8; ni++) {
            int col = wn + ni * 8 + g;
            b[ni][0] = Bs[st][tig * LDB8 + col];
            b[ni][1] = Bs[st][(tig + 4) * LDB8 + col];
        }
        #pragma unroll
        for (int mi = 0; mi < 4; mi++)
            #pragma unroll
            for (int ni = 0; ni < 8; ni++)
                mma8(acc[mi][ni], a[mi], b[ni]);
    }

    #pragma unroll
    for (int mi = 0; mi < 4; mi++)
        #pragma unroll
        for (int rr = 0; rr < 2; rr++) {
            int gm = m0 + wm + mi * 16 + g + rr * 8;
            #pragma unroll
            for (int ni = 0; ni < 8; ni++) {
                int c = n0 + wn + ni * 8 + tig * 2;
                float2 v = { acc[mi][ni][rr * 2] + bp[c],
                             acc[mi][ni][rr * 2 + 1] + bp[c + 1] };
                *(float2*)&out[(size_t)gm * EMB + c] = v;
            }
        }
}

// ---------------------------------------------------------------------------
extern "C" void kernel_launch(void* const* d_in, const int* in_sizes, int n_in,
                              void* d_out, int out_size)
{
    const float* x   = (const float*)d_in[0];
    const float* Wqk = (const float*)d_in[1];
    const float* bqk = (const float*)d_in[2];
    const float* Wv  = (const float*)d_in[3];
    const float* bv  = (const float*)d_in[4];
    const float* Wp  = (const float*)d_in[5];
    const float* bp  = (const float*)d_in[6];
    float* out = (float*)d_out;

    float *dX, *dWqk, *dWv, *dWp;
    cudaGetSymbolAddress((void**)&dX,   g_X);
    cudaGetSymbolAddress((void**)&dWqk, g_Wqk);
    cudaGetSymbolAddress((void**)&dWv,  g_Wv);
    cudaGetSymbolAddress((void**)&dWp,  g_Wp);

    {
        int n4;
        n4 = MTOT * EMB / 4;      round_kernel<<<(n4 + 255) / 256, 256>>>(x,   dX,   n4);
        n4 = EMB * 2 * EMB / 4;   round_kernel<<<(n4 + 255) / 256, 256>>>(Wqk, dWqk, n4);
        n4 = EMB * EMB / 4;       round_kernel<<<(n4 + 255) / 256, 256>>>(Wv,  dWv,  n4);
        n4 = EMB * EMB / 4;       round_kernel<<<(n4 + 255) / 256, 256>>>(Wp,  dWp,  n4);
    }

    dim3 g1(MTOT / 128, 18);
    qkv_kernel<<<g1, 128>>>(bqk, bv);

    dim3 g2(SEQ / 128, BH);
    flash_kernel<<<g2, 128>>>();

    dim3 g4(MTOT / 128, EMB / 128);
    proj_kernel<<<g4, 128>>>(bp, out);
}